// round 1
// baseline (speedup 1.0000x reference)
#include <cuda_runtime.h>
#include <cuda_bf16.h>

// Fused SConv: transform(3x3 lin-comb + sort8) -> GEMM (M=128,K=576,N=B*H*W)
// fp32 throughout; GEMM inner loop uses packed fma.rn.f32x2 (pairs over M).

#define TN 64          // pixels per CTA
#define NTHREADS 256
#define ZS_FLOATS (576 * TN)          // 36864
#define BUF_FLOATS (64 * 198)         // 12672 (x stage) >= 64*130 (W chunk)
#define COEF_OFF (ZS_FLOATS + BUF_FLOATS)
#define SMEM_FLOATS (COEF_OFF + 96)
#define SMEM_BYTES (SMEM_FLOATS * 4)

__device__ __forceinline__ unsigned long long pk2(float x) {
    unsigned long long r;
    asm("mov.b64 %0, {%1, %1};" : "=l"(r) : "f"(x));
    return r;
}
__device__ __forceinline__ unsigned long long fma2(unsigned long long a,
                                                   unsigned long long b,
                                                   unsigned long long c) {
    unsigned long long d;
    asm("fma.rn.f32x2 %0, %1, %2, %3;" : "=l"(d) : "l"(a), "l"(b), "l"(c));
    return d;
}

union U64F2 { unsigned long long u; float2 f; };

__global__ __launch_bounds__(NTHREADS, 1)
void sconv_fused_kernel(const float* __restrict__ xg,
                        const float* __restrict__ coefg,
                        const float* __restrict__ wg,
                        const float* __restrict__ biasg,
                        float* __restrict__ outg) {
    extern __shared__ float smem[];
    float* zs   = smem;                 // [576][64]
    float* buf  = smem + ZS_FLOATS;     // x stage [64][3][66] then W chunk [64][130]
    float* cf   = smem + COEF_OFF;      // 81 floats

    const int t  = threadIdx.x;
    const int b  = blockIdx.z;
    const int h  = blockIdx.y;
    const int w0 = blockIdx.x * TN;

    if (t < 81) cf[t] = coefg[t];

    // ---- stage x halo tile: buf[c*198 + r*66 + col] = x[b,c,h+r-1, w0-1+col]
    {
        const float* xb = xg + (long long)b * 64 * 128 * 128;
        for (int idx = t; idx < 64 * 198; idx += NTHREADS) {
            int c   = idx / 198;
            int rem = idx - c * 198;
            int r   = rem / 66;
            int col = rem - r * 66;
            int gr  = h + r - 1;
            int gc  = w0 - 1 + col;
            float val = 0.0f;
            if ((unsigned)gr < 128u && (unsigned)gc < 128u)
                val = xb[(c * 128 + gr) * 128 + gc];
            buf[idx] = val;
        }
    }
    __syncthreads();

    // ---- transform: per (c, nn) compute 9 z values into zs[(c*9+p)][nn]
#pragma unroll 1
    for (int it = 0; it < (64 * TN) / NTHREADS; ++it) {
        int item = t + it * NTHREADS;
        int c  = item >> 6;
        int nn = item & 63;
        const float* xr = &buf[c * 198];
        float v0 = xr[nn],       v1 = xr[nn + 1],       v2 = xr[nn + 2];
        float v3 = xr[66 + nn],  v4 = xr[66 + nn + 1],  v5 = xr[66 + nn + 2];
        float v6 = xr[132 + nn], v7 = xr[132 + nn + 1], v8 = xr[132 + nn + 2];

        float yv[8];
#pragma unroll
        for (int q = 0; q < 8; ++q) {
            int ri = q + (q >= 4 ? 1 : 0);   // rows 0,1,2,3,5,6,7,8
            const float* cr = &cf[ri * 9];
            float s = cr[0] * v0;
            s = fmaf(cr[1], v1, s); s = fmaf(cr[2], v2, s);
            s = fmaf(cr[3], v3, s); s = fmaf(cr[4], v4, s);
            s = fmaf(cr[5], v5, s); s = fmaf(cr[6], v6, s);
            s = fmaf(cr[7], v7, s); s = fmaf(cr[8], v8, s);
            yv[q] = s;
        }
        // Batcher odd-even mergesort, 8 elements, 19 comparators, ascending
#define CS(a, b) { float _l = fminf(yv[a], yv[b]); float _h = fmaxf(yv[a], yv[b]); yv[a] = _l; yv[b] = _h; }
        CS(0,1) CS(2,3) CS(4,5) CS(6,7)
        CS(0,2) CS(1,3) CS(4,6) CS(5,7)
        CS(1,2) CS(5,6)
        CS(0,4) CS(1,5) CS(2,6) CS(3,7)
        CS(2,4) CS(3,5)
        CS(1,2) CS(3,4) CS(5,6)
#undef CS
        float* zr = &zs[(c * 9) * TN + nn];
        zr[0 * TN] = yv[0]; zr[1 * TN] = yv[1]; zr[2 * TN] = yv[2]; zr[3 * TN] = yv[3];
        zr[4 * TN] = v4;
        zr[5 * TN] = yv[4]; zr[6 * TN] = yv[5]; zr[7 * TN] = yv[6]; zr[8 * TN] = yv[7];
    }
    __syncthreads();

    // ---- GEMM: out[m, n] = sum_k W[m,k] * zs[k,n]   (m in 0..127, n tile of 64)
    const int tx = t & 15;          // n group
    const int ty = t >> 4;          // m group
    const int m0 = ty * 8;
    const int n0 = tx * 4;

    unsigned long long acc[4][4];   // [m-pair][n] ; each holds {out[m0+2i], out[m0+2i+1]}
#pragma unroll
    for (int i = 0; i < 4; ++i)
#pragma unroll
        for (int j = 0; j < 4; ++j) acc[i][j] = 0ULL;

    float* Ws = buf;                // [64][130]

    for (int ch = 0; ch < 9; ++ch) {
        // stage W chunk: Ws[kk][m] = W[m, ch*64 + kk]
#pragma unroll
        for (int i = 0; i < 8; ++i) {
            int idx = t + i * NTHREADS;       // 0..2047
            int m = idx >> 4;
            int f = idx & 15;
            float4 wv = *reinterpret_cast<const float4*>(wg + m * 576 + ch * 64 + f * 4);
            Ws[(f * 4 + 0) * 130 + m] = wv.x;
            Ws[(f * 4 + 1) * 130 + m] = wv.y;
            Ws[(f * 4 + 2) * 130 + m] = wv.z;
            Ws[(f * 4 + 3) * 130 + m] = wv.w;
        }
        __syncthreads();

        const float* zbase = zs + ch * 64 * TN + n0;
#pragma unroll 8
        for (int kk = 0; kk < 64; ++kk) {
            float4 zv = *reinterpret_cast<const float4*>(zbase + kk * TN);
            unsigned long long zz0 = pk2(zv.x), zz1 = pk2(zv.y),
                               zz2 = pk2(zv.z), zz3 = pk2(zv.w);
            const unsigned long long* wp =
                reinterpret_cast<const unsigned long long*>(&Ws[kk * 130 + m0]);
            unsigned long long wv0 = wp[0], wv1 = wp[1], wv2 = wp[2], wv3 = wp[3];
            acc[0][0] = fma2(wv0, zz0, acc[0][0]);
            acc[0][1] = fma2(wv0, zz1, acc[0][1]);
            acc[0][2] = fma2(wv0, zz2, acc[0][2]);
            acc[0][3] = fma2(wv0, zz3, acc[0][3]);
            acc[1][0] = fma2(wv1, zz0, acc[1][0]);
            acc[1][1] = fma2(wv1, zz1, acc[1][1]);
            acc[1][2] = fma2(wv1, zz2, acc[1][2]);
            acc[1][3] = fma2(wv1, zz3, acc[1][3]);
            acc[2][0] = fma2(wv2, zz0, acc[2][0]);
            acc[2][1] = fma2(wv2, zz1, acc[2][1]);
            acc[2][2] = fma2(wv2, zz2, acc[2][2]);
            acc[2][3] = fma2(wv2, zz3, acc[2][3]);
            acc[3][0] = fma2(wv3, zz0, acc[3][0]);
            acc[3][1] = fma2(wv3, zz1, acc[3][1]);
            acc[3][2] = fma2(wv3, zz2, acc[3][2]);
            acc[3][3] = fma2(wv3, zz3, acc[3][3]);
        }
        __syncthreads();   // before next chunk overwrites Ws
    }

    // ---- epilogue: bias + store (float4 per m-row, coalesced over tx)
#pragma unroll
    for (int i = 0; i < 4; ++i) {
        int mlo = m0 + 2 * i;
        float blo = biasg[mlo];
        float bhi = biasg[mlo + 1];
        U64F2 a0, a1, a2, a3;
        a0.u = acc[i][0]; a1.u = acc[i][1]; a2.u = acc[i][2]; a3.u = acc[i][3];
        float4 rlo = make_float4(a0.f.x + blo, a1.f.x + blo, a2.f.x + blo, a3.f.x + blo);
        float4 rhi = make_float4(a0.f.y + bhi, a1.f.y + bhi, a2.f.y + bhi, a3.f.y + bhi);
        long long base_lo = (((long long)b * 128 + mlo) * 128 + h) * 128 + w0 + n0;
        long long base_hi = base_lo + 128LL * 128;   // next m row
        *reinterpret_cast<float4*>(outg + base_lo) = rlo;
        *reinterpret_cast<float4*>(outg + base_hi) = rhi;
    }
}

extern "C" void kernel_launch(void* const* d_in, const int* in_sizes, int n_in,
                              void* d_out, int out_size) {
    const float *x = nullptr, *coef = nullptr, *w = nullptr, *bias = nullptr;
    for (int i = 0; i < n_in; ++i) {
        switch (in_sizes[i]) {
            case 8388608: x    = (const float*)d_in[i]; break;  // 8*64*128*128
            case 81:      coef = (const float*)d_in[i]; break;
            case 73728:   w    = (const float*)d_in[i]; break;  // 128*64*9
            case 128:     bias = (const float*)d_in[i]; break;
        }
    }
    cudaFuncSetAttribute(sconv_fused_kernel,
                         cudaFuncAttributeMaxDynamicSharedMemorySize, SMEM_BYTES);
    dim3 grid(128 / TN, 128, 8);   // (w tiles, h, b)
    sconv_fused_kernel<<<grid, NTHREADS, SMEM_BYTES>>>(x, coef, w, bias, (float*)d_out);
}

// round 5
// speedup vs baseline: 1.4967x; 1.4967x over previous
#include <cuda_runtime.h>
#include <cuda_bf16.h>
#include <cstdint>

// Fused SConv via warp-level bf16 mma.sync split-precision GEMM (sm_103 baseline PTX).
// out[m=128, n] = sum_k W[m,k] * z[k,n], K=576, 64 pixels per CTA.
// fp32 -> (hi,lo) bf16; D = Whi*Zhi + Whi*Zlo + Wlo*Zhi.

#define NTHREADS 256
#define ZSTRIDE 1168        // bytes per z row (576*2 + 16 pad) -> ldmatrix conflict-free
#define WSTRIDE 144         // bytes per W row (64*2 + 16 pad)

#define OFF_ZHI 0                       // 64 x 1168 = 74752
#define OFF_ZLO 74752                   // 74752
#define OFF_W   149504                  // 2 buffers x (18432 hi + 18432 lo) = 73728
#define OFF_XS  149504                  // x halo stage 50688 (overlaps W; protected by syncthreads)
#define OFF_OB  149504                  // epilogue [64][129] f32 (overlaps W, after GEMM)
#define OFF_CF  223232                  // 81 floats
#define SMEM_BYTES 223744

__device__ __align__(16) unsigned char g_Whi[9 * 18432];
__device__ __align__(16) unsigned char g_Wlo[9 * 18432];

__device__ __forceinline__ uint32_t smem_u32(const void* p) {
    uint32_t a;
    asm("{ .reg .u64 t; cvta.to.shared.u64 t, %1; cvt.u32.u64 %0, t; }" : "=r"(a) : "l"(p));
    return a;
}

__device__ __forceinline__ void ldm_x4(uint32_t* r, uint32_t addr) {
    asm volatile("ldmatrix.sync.aligned.m8n8.x4.shared.b16 {%0,%1,%2,%3}, [%4];"
                 : "=r"(r[0]), "=r"(r[1]), "=r"(r[2]), "=r"(r[3]) : "r"(addr));
}
__device__ __forceinline__ void ldm_x2(uint32_t* r, uint32_t addr) {
    asm volatile("ldmatrix.sync.aligned.m8n8.x2.shared.b16 {%0,%1}, [%2];"
                 : "=r"(r[0]), "=r"(r[1]) : "r"(addr));
}
__device__ __forceinline__ void mma16816(float* d, const uint32_t* a, const uint32_t* b) {
    asm volatile("mma.sync.aligned.m16n8k16.row.col.f32.bf16.bf16.f32 "
                 "{%0,%1,%2,%3}, {%4,%5,%6,%7}, {%8,%9}, {%0,%1,%2,%3};"
                 : "+f"(d[0]), "+f"(d[1]), "+f"(d[2]), "+f"(d[3])
                 : "r"(a[0]), "r"(a[1]), "r"(a[2]), "r"(a[3]), "r"(b[0]), "r"(b[1]));
}
__device__ __forceinline__ void cp16(uint32_t saddr, const void* gaddr) {
    asm volatile("cp.async.ca.shared.global [%0], [%1], 16;" :: "r"(saddr), "l"(gaddr));
}
#define CP_COMMIT() asm volatile("cp.async.commit_group;" ::: "memory")
#define CP_WAIT0()  asm volatile("cp.async.wait_group 0;" ::: "memory")

// ---------------- W pre-split kernel (padded [ch][m][144B] layout) ----------------
__global__ void presplit_w(const float* __restrict__ wg) {
    int idx = blockIdx.x * blockDim.x + threadIdx.x;   // 73728
    int ch = idx >> 13;
    int m  = (idx >> 6) & 127;
    int kk = idx & 63;
    float v = wg[m * 576 + ch * 64 + kk];
    __nv_bfloat16 hi = __float2bfloat16(v);
    __nv_bfloat16 lo = __float2bfloat16(v - __bfloat162float(hi));
    int off = ch * 18432 + m * WSTRIDE + kk * 2;
    *reinterpret_cast<__nv_bfloat16*>(g_Whi + off) = hi;
    *reinterpret_cast<__nv_bfloat16*>(g_Wlo + off) = lo;
}

// ---------------- stage one W chunk (hi+lo, 36864B) via cp.async ----------------
__device__ __forceinline__ void stage_w(uint32_t sb, int t, int ch, int buf) {
#pragma unroll
    for (int i = 0; i < 9; ++i) {
        int idx2 = t + i * NTHREADS;            // 0..2303
        int half = idx2 >= 1152;
        int off16 = (idx2 - half * 1152) * 16;
        const unsigned char* gsrc = (half ? g_Wlo : g_Whi) + ch * 18432 + off16;
        uint32_t sdst = sb + OFF_W + buf * 36864 + half * 18432 + off16;
        cp16(sdst, gsrc);
    }
    CP_COMMIT();
}

// ---------------- main fused kernel ----------------
__global__ __launch_bounds__(NTHREADS, 1)
void sconv_mma_kernel(const float* __restrict__ xg,
                      const float* __restrict__ coefg,
                      const float* __restrict__ biasg,
                      float* __restrict__ outg) {
    extern __shared__ __align__(1024) unsigned char smem[];
    const uint32_t sb = smem_u32(smem);
    const int t   = threadIdx.x;
    const int wid = t >> 5;
    const int lid = t & 31;
    const int b   = blockIdx.z;
    const int h   = blockIdx.y;
    const int w0  = blockIdx.x * 64;

    float* cf = reinterpret_cast<float*>(smem + OFF_CF);
    float* xs = reinterpret_cast<float*>(smem + OFF_XS);

    if (t < 81) cf[t] = coefg[t];

    // ---- stage x halo tile: xs[c*198 + r*66 + col] = x[b,c,h+r-1,w0-1+col]
    {
        const float* xb = xg + (long long)b * 64 * 128 * 128;
        for (int idx = t; idx < 64 * 198; idx += NTHREADS) {
            int c   = idx / 198;
            int rem = idx - c * 198;
            int r   = rem / 66;
            int col = rem - r * 66;
            int gr  = h + r - 1;
            int gc  = w0 - 1 + col;
            float val = 0.0f;
            if ((unsigned)gr < 128u && (unsigned)gc < 128u)
                val = xb[(c * 128 + gr) * 128 + gc];
            xs[idx] = val;
        }
    }
    __syncthreads();

    // ---- transform: (c, nn) -> 9 z values -> bf16 hi/lo into z[nn][k] rows
#pragma unroll 1
    for (int it = 0; it < 16; ++it) {
        int c  = lid + ((it & 1) << 5);
        int nn = wid + ((it >> 1) << 3);
        const float* xr = &xs[c * 198];
        float v0 = xr[nn],       v1 = xr[nn + 1],       v2 = xr[nn + 2];
        float v3 = xr[66 + nn],  v4 = xr[66 + nn + 1],  v5 = xr[66 + nn + 2];
        float v6 = xr[132 + nn], v7 = xr[132 + nn + 1], v8 = xr[132 + nn + 2];

        float yv[8];
#pragma unroll
        for (int q = 0; q < 8; ++q) {
            int ri = q + (q >= 4 ? 1 : 0);
            const float* cr = &cf[ri * 9];
            float s = cr[0] * v0;
            s = fmaf(cr[1], v1, s); s = fmaf(cr[2], v2, s);
            s = fmaf(cr[3], v3, s); s = fmaf(cr[4], v4, s);
            s = fmaf(cr[5], v5, s); s = fmaf(cr[6], v6, s);
            s = fmaf(cr[7], v7, s); s = fmaf(cr[8], v8, s);
            yv[q] = s;
        }
#define CS(a, bb) { float _l = fminf(yv[a], yv[bb]); float _h = fmaxf(yv[a], yv[bb]); yv[a] = _l; yv[bb] = _h; }
        CS(0,1) CS(2,3) CS(4,5) CS(6,7)
        CS(0,2) CS(1,3) CS(4,6) CS(5,7)
        CS(1,2) CS(5,6)
        CS(0,4) CS(1,5) CS(2,6) CS(3,7)
        CS(2,4) CS(3,5)
        CS(1,2) CS(3,4) CS(5,6)
#undef CS
        float vals[9] = { yv[0], yv[1], yv[2], yv[3], v4, yv[4], yv[5], yv[6], yv[7] };

        unsigned char* zhb = smem + OFF_ZHI + nn * ZSTRIDE + c * 18;
        unsigned char* zlb = smem + OFF_ZLO + nn * ZSTRIDE + c * 18;
#pragma unroll
        for (int p = 0; p < 9; ++p) {
            float v = vals[p];
            __nv_bfloat16 hi = __float2bfloat16(v);
            __nv_bfloat16 lo = __float2bfloat16(v - __bfloat162float(hi));
            *reinterpret_cast<__nv_bfloat16*>(zhb + p * 2) = hi;
            *reinterpret_cast<__nv_bfloat16*>(zlb + p * 2) = lo;
        }
    }

    // RACE FIX: all warps must finish reading xs before W chunk 0 (which
    // aliases xs) is staged. This was the R4 rel_err=1.46e-2 bug.
    __syncthreads();
    stage_w(sb, t, 0, 0);

    // ---- GEMM: mma.m16n8k16; A = z[n][k] (row), B = W[m][k] (col k x m)
    const int nt = wid & 3;            // n-tile (16 rows)
    const int mh = wid >> 2;           // m half (64 cols)
    const int n0 = nt * 16;
    const int mbase = mh * 64;

    float acc[8][4];
#pragma unroll
    for (int i = 0; i < 8; ++i)
#pragma unroll
        for (int j = 0; j < 4; ++j) acc[i][j] = 0.0f;

    const int rA   = lid & 7;
    const int matA = lid >> 3;
    const int nrow = n0 + rA + ((matA & 1) << 3);
    const int kaddA = (matA >> 1) << 3;
    const uint32_t aBase = sb + OFF_ZHI + nrow * ZSTRIDE;
    const int rB  = lid & 7;
    const int selB = (lid >> 3) & 1;

    for (int ch = 0; ch < 9; ++ch) {
        int buf = ch & 1;
        CP_WAIT0();
        __syncthreads();
        if (ch < 8) stage_w(sb, t, ch + 1, buf ^ 1);

        const uint32_t wHiB = sb + OFF_W + buf * 36864;
        const uint32_t wLoB = wHiB + 18432;

#pragma unroll
        for (int ks = 0; ks < 4; ++ks) {
            uint32_t aAddr = aBase + (ch * 64 + ks * 16 + kaddA) * 2;
            uint32_t ahi[4], alo[4];
            ldm_x4(ahi, aAddr);
            ldm_x4(alo, aAddr + (OFF_ZLO - OFF_ZHI));

#pragma unroll
            for (int mb = 0; mb < 8; ++mb) {
                uint32_t rowOff = (mbase + mb * 8 + rB) * WSTRIDE + (ks * 16 + selB * 8) * 2;
                uint32_t bhi[2], blo[2];
                ldm_x2(bhi, wHiB + rowOff);
                ldm_x2(blo, wLoB + rowOff);
                mma16816(acc[mb], ahi, bhi);
                mma16816(acc[mb], ahi, blo);
                mma16816(acc[mb], alo, bhi);
            }
        }
    }
    __syncthreads();   // all mma done; W region reusable as epilogue buffer

    // ---- epilogue: fragments -> smem [n][129] f32 -> coalesced float4 stores
    float* ob = reinterpret_cast<float*>(smem + OFF_OB);
    {
        int nr = n0 + (lid >> 2);
        int mc0 = mbase + ((lid & 3) << 1);
#pragma unroll
        for (int mb = 0; mb < 8; ++mb) {
            int mc = mc0 + mb * 8;
            ob[nr * 129 + mc]           = acc[mb][0];
            ob[nr * 129 + mc + 1]       = acc[mb][1];
            ob[(nr + 8) * 129 + mc]     = acc[mb][2];
            ob[(nr + 8) * 129 + mc + 1] = acc[mb][3];
        }
    }
    __syncthreads();

#pragma unroll 1
    for (int it = 0; it < 8; ++it) {
        int m = it * 16 + (t >> 4);
        int g = t & 15;
        float bv = __ldg(biasg + m);
        int n0s = g * 4;
        float4 o;
        o.x = ob[(n0s + 0) * 129 + m] + bv;
        o.y = ob[(n0s + 1) * 129 + m] + bv;
        o.z = ob[(n0s + 2) * 129 + m] + bv;
        o.w = ob[(n0s + 3) * 129 + m] + bv;
        long long obase = (((long long)b * 128 + m) * 128 + h) * 128 + w0 + n0s;
        *reinterpret_cast<float4*>(outg + obase) = o;
    }
}

extern "C" void kernel_launch(void* const* d_in, const int* in_sizes, int n_in,
                              void* d_out, int out_size) {
    const float *x = nullptr, *coef = nullptr, *w = nullptr, *bias = nullptr;
    for (int i = 0; i < n_in; ++i) {
        switch (in_sizes[i]) {
            case 8388608: x    = (const float*)d_in[i]; break;
            case 81:      coef = (const float*)d_in[i]; break;
            case 73728:   w    = (const float*)d_in[i]; break;
            case 128:     bias = (const float*)d_in[i]; break;
        }
    }
    presplit_w<<<72, 1024>>>(w);
    cudaFuncSetAttribute(sconv_mma_kernel,
                         cudaFuncAttributeMaxDynamicSharedMemorySize, SMEM_BYTES);
    dim3 grid(2, 128, 8);
    sconv_mma_kernel<<<grid, NTHREADS, SMEM_BYTES>>>(x, coef, bias, (float*)d_out);
}

// round 7
// speedup vs baseline: 1.6580x; 1.1078x over previous
#include <cuda_runtime.h>
#include <cuda_bf16.h>
#include <cstdint>

// Fused SConv via warp-level bf16 mma.sync split-precision GEMM (sm_103 baseline PTX).
// out[m=128, n] = sum_k W[m,k] * z[k,n], K=576, 64 pixels per CTA.
// fp32 -> (hi,lo) bf16; D = Whi*Zhi + Whi*Zlo + Wlo*Zhi.
// R6: 512 threads (16 warps), B via ldmatrix.x4 over two m-blocks.

#define NTHREADS 512
#define ZSTRIDE 1168        // bytes per z row (576*2 + 16 pad) -> ldmatrix conflict-free
#define WSTRIDE 144         // bytes per W row (64*2 + 16 pad)

#define OFF_ZHI 0                       // 64 x 1168 = 74752
#define OFF_ZLO 74752                   // 74752
#define OFF_W   149504                  // 2 buffers x (18432 hi + 18432 lo) = 73728
#define OFF_XS  149504                  // x halo stage 50688 (overlaps W; sync-protected)
#define OFF_OB  149504                  // epilogue [64][129] f32 (overlaps W, after GEMM)
#define OFF_CF  223232                  // 81 floats
#define SMEM_BYTES 223744

__device__ __align__(16) unsigned char g_Whi[9 * 18432];
__device__ __align__(16) unsigned char g_Wlo[9 * 18432];

__device__ __forceinline__ uint32_t smem_u32(const void* p) {
    uint32_t a;
    asm("{ .reg .u64 t; cvta.to.shared.u64 t, %1; cvt.u32.u64 %0, t; }" : "=r"(a) : "l"(p));
    return a;
}

__device__ __forceinline__ void ldm_x4(uint32_t* r, uint32_t addr) {
    asm volatile("ldmatrix.sync.aligned.m8n8.x4.shared.b16 {%0,%1,%2,%3}, [%4];"
                 : "=r"(r[0]), "=r"(r[1]), "=r"(r[2]), "=r"(r[3]) : "r"(addr));
}
__device__ __forceinline__ void mma16816(float* d, const uint32_t* a, const uint32_t* b) {
    asm volatile("mma.sync.aligned.m16n8k16.row.col.f32.bf16.bf16.f32 "
                 "{%0,%1,%2,%3}, {%4,%5,%6,%7}, {%8,%9}, {%0,%1,%2,%3};"
                 : "+f"(d[0]), "+f"(d[1]), "+f"(d[2]), "+f"(d[3])
                 : "r"(a[0]), "r"(a[1]), "r"(a[2]), "r"(a[3]), "r"(b[0]), "r"(b[1]));
}
__device__ __forceinline__ void cp16(uint32_t saddr, const void* gaddr) {
    asm volatile("cp.async.ca.shared.global [%0], [%1], 16;" :: "r"(saddr), "l"(gaddr));
}
#define CP_COMMIT() asm volatile("cp.async.commit_group;" ::: "memory")
#define CP_WAIT0()  asm volatile("cp.async.wait_group 0;" ::: "memory")

// ---------------- W pre-split kernel (padded [ch][m][144B] layout) ----------------
__global__ void presplit_w(const float* __restrict__ wg) {
    int idx = blockIdx.x * blockDim.x + threadIdx.x;   // 73728
    int ch = idx >> 13;
    int m  = (idx >> 6) & 127;
    int kk = idx & 63;
    float v = wg[m * 576 + ch * 64 + kk];
    __nv_bfloat16 hi = __float2bfloat16(v);
    __nv_bfloat16 lo = __float2bfloat16(v - __bfloat162float(hi));
    int off = ch * 18432 + m * WSTRIDE + kk * 2;
    *reinterpret_cast<__nv_bfloat16*>(g_Whi + off) = hi;
    *reinterpret_cast<__nv_bfloat16*>(g_Wlo + off) = lo;
}

// ---------------- stage one W chunk (hi+lo, 36864B = 2304 x 16B) ----------------
__device__ __forceinline__ void stage_w(uint32_t sb, int t, int ch, int buf) {
#pragma unroll
    for (int i = 0; i < 5; ++i) {
        int idx2 = t + i * NTHREADS;            // 0..2559, valid < 2304
        if (idx2 < 2304) {
            int half = idx2 >= 1152;
            int off16 = (idx2 - half * 1152) * 16;
            const unsigned char* gsrc = (half ? g_Wlo : g_Whi) + ch * 18432 + off16;
            uint32_t sdst = sb + OFF_W + buf * 36864 + half * 18432 + off16;
            cp16(sdst, gsrc);
        }
    }
    CP_COMMIT();
}

// ---------------- main fused kernel ----------------
__global__ __launch_bounds__(NTHREADS, 1)
void sconv_mma_kernel(const float* __restrict__ xg,
                      const float* __restrict__ coefg,
                      const float* __restrict__ biasg,
                      float* __restrict__ outg) {
    extern __shared__ __align__(1024) unsigned char smem[];
    const uint32_t sb = smem_u32(smem);
    const int t   = threadIdx.x;
    const int wid = t >> 5;
    const int lid = t & 31;
    const int b   = blockIdx.z;
    const int h   = blockIdx.y;
    const int w0  = blockIdx.x * 64;

    float* cf = reinterpret_cast<float*>(smem + OFF_CF);
    float* xs = reinterpret_cast<float*>(smem + OFF_XS);

    if (t < 81) cf[t] = coefg[t];

    // ---- stage x halo tile: xs[c*198 + r*66 + col] = x[b,c,h+r-1,w0-1+col]
    {
        const float* xb = xg + (long long)b * 64 * 128 * 128;
        for (int idx = t; idx < 64 * 198; idx += NTHREADS) {
            int c   = idx / 198;
            int rem = idx - c * 198;
            int r   = rem / 66;
            int col = rem - r * 66;
            int gr  = h + r - 1;
            int gc  = w0 - 1 + col;
            float val = 0.0f;
            if ((unsigned)gr < 128u && (unsigned)gc < 128u)
                val = xb[(c * 128 + gr) * 128 + gc];
            xs[idx] = val;
        }
    }
    __syncthreads();

    // ---- transform: (c, nn) -> 9 z values -> bf16 hi/lo into z[nn][k] rows
#pragma unroll 1
    for (int it = 0; it < 8; ++it) {
        int c  = lid + ((it & 1) << 5);            // 0..63
        int nn = wid + ((it >> 1) << 4);           // 0..63
        const float* xr = &xs[c * 198];
        float v0 = xr[nn],       v1 = xr[nn + 1],       v2 = xr[nn + 2];
        float v3 = xr[66 + nn],  v4 = xr[66 + nn + 1],  v5 = xr[66 + nn + 2];
        float v6 = xr[132 + nn], v7 = xr[132 + nn + 1], v8 = xr[132 + nn + 2];

        float yv[8];
#pragma unroll
        for (int q = 0; q < 8; ++q) {
            int ri = q + (q >= 4 ? 1 : 0);
            const float* cr = &cf[ri * 9];
            float s = cr[0] * v0;
            s = fmaf(cr[1], v1, s); s = fmaf(cr[2], v2, s);
            s = fmaf(cr[3], v3, s); s = fmaf(cr[4], v4, s);
            s = fmaf(cr[5], v5, s); s = fmaf(cr[6], v6, s);
            s = fmaf(cr[7], v7, s); s = fmaf(cr[8], v8, s);
            yv[q] = s;
        }
#define CS(a, bb) { float _l = fminf(yv[a], yv[bb]); float _h = fmaxf(yv[a], yv[bb]); yv[a] = _l; yv[bb] = _h; }
        CS(0,1) CS(2,3) CS(4,5) CS(6,7)
        CS(0,2) CS(1,3) CS(4,6) CS(5,7)
        CS(1,2) CS(5,6)
        CS(0,4) CS(1,5) CS(2,6) CS(3,7)
        CS(2,4) CS(3,5)
        CS(1,2) CS(3,4) CS(5,6)
#undef CS
        float vals[9] = { yv[0], yv[1], yv[2], yv[3], v4, yv[4], yv[5], yv[6], yv[7] };

        unsigned char* zhb = smem + OFF_ZHI + nn * ZSTRIDE + c * 18;
        unsigned char* zlb = smem + OFF_ZLO + nn * ZSTRIDE + c * 18;
#pragma unroll
        for (int p = 0; p < 9; ++p) {
            float v = vals[p];
            __nv_bfloat16 hi = __float2bfloat16(v);
            __nv_bfloat16 lo = __float2bfloat16(v - __bfloat162float(hi));
            *reinterpret_cast<__nv_bfloat16*>(zhb + p * 2) = hi;
            *reinterpret_cast<__nv_bfloat16*>(zlb + p * 2) = lo;
        }
    }

    // xs aliases W buffer 0: all reads of xs must complete before staging.
    __syncthreads();
    stage_w(sb, t, 0, 0);

    // ---- GEMM: mma.m16n8k16; A = z[n][k] rows, B = W[m][k] rows (k x m col frags)
    const int nt = wid & 3;            // n-tile (16 rows)
    const int mq = wid >> 2;           // m quarter (32 cols)
    const int n0 = nt * 16;
    const int mbase = mq * 32;

    float acc[4][4];
#pragma unroll
    for (int i = 0; i < 4; ++i)
#pragma unroll
        for (int j = 0; j < 4; ++j) acc[i][j] = 0.0f;

    // A x4 addressing (16n x 16k): mats {n0..7 klo, n8..15 klo? no: rows n, k halves}
    const int rA   = lid & 7;
    const int matA = lid >> 3;
    const int nrow = n0 + rA + ((matA & 1) << 3);
    const int kaddA = (matA >> 1) << 3;
    const uint32_t aBase = sb + OFF_ZHI + nrow * ZSTRIDE;

    // B x4 addressing: mats {m p*16+0..7 klo, same khi, m +8 klo, m +8 khi}
    const int gB = lid >> 3;
    const int rB = lid & 7;
    const uint32_t bRowOff = (((gB & 2) << 2) + rB) * WSTRIDE + ((gB & 1) << 4);

    for (int ch = 0; ch < 9; ++ch) {
        int buf = ch & 1;
        CP_WAIT0();
        __syncthreads();
        if (ch < 8) stage_w(sb, t, ch + 1, buf ^ 1);

        const uint32_t wHiB = sb + OFF_W + buf * 36864 + mbase * WSTRIDE + bRowOff;
        const uint32_t wLoB = wHiB + 18432;

#pragma unroll
        for (int ks = 0; ks < 4; ++ks) {
            uint32_t aAddr = aBase + (ch * 64 + ks * 16 + kaddA) * 2;
            uint32_t ahi[4], alo[4];
            ldm_x4(ahi, aAddr);
            ldm_x4(alo, aAddr + (OFF_ZLO - OFF_ZHI));

#pragma unroll
            for (int p = 0; p < 2; ++p) {
                uint32_t off = p * (16 * WSTRIDE) + ks * 32;
                uint32_t bhi[4], blo[4];
                ldm_x4(bhi, wHiB + off);
                ldm_x4(blo, wLoB + off);
                mma16816(acc[2 * p],     ahi, bhi);
                mma16816(acc[2 * p],     ahi, blo + 0);
                mma16816(acc[2 * p],     alo, bhi);
                mma16816(acc[2 * p + 1], ahi, bhi + 2);
                mma16816(acc[2 * p + 1], ahi, blo + 2);
                mma16816(acc[2 * p + 1], alo, bhi + 2);
            }
        }
    }
    __syncthreads();   // all mma done; W region reusable as epilogue buffer

    // ---- epilogue: fragments -> smem [n][129] f32 -> coalesced float4 stores
    float* ob = reinterpret_cast<float*>(smem + OFF_OB);
    {
        int nr = n0 + (lid >> 2);
        int mc0 = mbase + ((lid & 3) << 1);
#pragma unroll
        for (int mb = 0; mb < 4; ++mb) {
            int mc = mc0 + mb * 8;
            ob[nr * 129 + mc]           = acc[mb][0];
            ob[nr * 129 + mc + 1]       = acc[mb][1];
            ob[(nr + 8) * 129 + mc]     = acc[mb][2];
            ob[(nr + 8) * 129 + mc + 1] = acc[mb][3];
        }
    }
    __syncthreads();

#pragma unroll 1
    for (int it = 0; it < 4; ++it) {
        int m = it * 32 + (t >> 4);
        int g = t & 15;
        float bv = __ldg(biasg + m);
        int n0s = g * 4;
        float4 o;
        o.x = ob[(n0s + 0) * 129 + m] + bv;
        o.y = ob[(n0s + 1) * 129 + m] + bv;
        o.z = ob[(n0s + 2) * 129 + m] + bv;
        o.w = ob[(n0s + 3) * 129 + m] + bv;
        long long obase = (((long long)b * 128 + m) * 128 + h) * 128 + w0 + n0s;
        *reinterpret_cast<float4*>(outg + obase) = o;
    }
}

extern "C" void kernel_launch(void* const* d_in, const int* in_sizes, int n_in,
                              void* d_out, int out_size) {
    const float *x = nullptr, *coef = nullptr, *w = nullptr, *bias = nullptr;
    for (int i = 0; i < n_in; ++i) {
        switch (in_sizes[i]) {
            case 8388608: x    = (const float*)d_in[i]; break;
            case 81:      coef = (const float*)d_in[i]; break;
            case 73728:   w    = (const float*)d_in[i]; break;
            case 128:     bias = (const float*)d_in[i]; break;
        }
    }
    presplit_w<<<72, 1024>>>(w);
    cudaFuncSetAttribute(sconv_mma_kernel,
                         cudaFuncAttributeMaxDynamicSharedMemorySize, SMEM_BYTES);
    dim3 grid(2, 128, 8);
    sconv_mma_kernel<<<grid, NTHREADS, SMEM_BYTES>>>(x, coef, bias, (float*)d_out);
}

// round 8
// speedup vs baseline: 2.0109x; 1.2128x over previous
#include <cuda_runtime.h>
#include <cuda_bf16.h>
#include <cstdint>

// Fused SConv via warp-level bf16 mma.sync split-precision GEMM.
// out[m=128, n] = sum_k W[m,k] * z[k,n], K=576, 128 pixels per CTA.
// fp32 -> (hi,lo) bf16; D = Whi*Zhi + Whi*Zlo + Wlo*Zhi.
// R8: 32n x 32m warp tiles, K chunked in halves (c 0..31 / 32..63),
//     u32-packed transform stores, 48k W chunks double-buffered.

#define NTHREADS 512
#define ZSTRIDE 592          // 288*2 + 16 pad  (ldmatrix conflict-free: 592%128=80)
#define WSTRIDE 112          // 48*2 + 16 pad   (112%128=112, conflict-free)
#define XC 393               // floats per channel in x stage (3 rows x 131)
#define XR 131

#define OFF_ZHI 0            // 128 x 592 = 75776
#define OFF_ZLO 75776        // 75776
#define OFF_W   151552       // 2 x 28672 W buffers = 57344
#define OFF_XS  151552       // 32*393*4 = 50304  (overlaps W; phase-separated)
#define OFF_OB  151552       // 64*129*4 = 33024  (overlaps W; after GEMM)
#define OFF_CF  208896       // 81 floats
#define SMEM_BYTES 209408

#define WCHUNK_BYTES 14336   // 128 m x 112 B (48 k values)
#define WBUF_BYTES   28672   // hi + lo

__device__ __align__(16) unsigned char g_Whi[12 * WCHUNK_BYTES];
__device__ __align__(16) unsigned char g_Wlo[12 * WCHUNK_BYTES];

__device__ __forceinline__ uint32_t smem_u32(const void* p) {
    uint32_t a;
    asm("{ .reg .u64 t; cvta.to.shared.u64 t, %1; cvt.u32.u64 %0, t; }" : "=r"(a) : "l"(p));
    return a;
}
__device__ __forceinline__ void ldm_x4(uint32_t* r, uint32_t addr) {
    asm volatile("ldmatrix.sync.aligned.m8n8.x4.shared.b16 {%0,%1,%2,%3}, [%4];"
                 : "=r"(r[0]), "=r"(r[1]), "=r"(r[2]), "=r"(r[3]) : "r"(addr));
}
__device__ __forceinline__ void mma16816(float* d, const uint32_t* a, const uint32_t* b) {
    asm volatile("mma.sync.aligned.m16n8k16.row.col.f32.bf16.bf16.f32 "
                 "{%0,%1,%2,%3}, {%4,%5,%6,%7}, {%8,%9}, {%0,%1,%2,%3};"
                 : "+f"(d[0]), "+f"(d[1]), "+f"(d[2]), "+f"(d[3])
                 : "r"(a[0]), "r"(a[1]), "r"(a[2]), "r"(a[3]), "r"(b[0]), "r"(b[1]));
}
__device__ __forceinline__ void cp16(uint32_t saddr, const void* gaddr) {
    asm volatile("cp.async.ca.shared.global [%0], [%1], 16;" :: "r"(saddr), "l"(gaddr));
}
#define CP_COMMIT() asm volatile("cp.async.commit_group;" ::: "memory")
#define CP_WAIT0()  asm volatile("cp.async.wait_group 0;" ::: "memory")

// ---------------- W pre-split kernel: [chunk 12][m 128][48k], 112B rows ----------------
__global__ void presplit_w(const float* __restrict__ wg) {
    int idx = blockIdx.x * blockDim.x + threadIdx.x;   // 73728
    int m  = idx / 576;
    int kk = idx - m * 576;
    int gc  = kk / 48;
    int kkl = kk - gc * 48;
    float v = wg[m * 576 + kk];
    __nv_bfloat16 hi = __float2bfloat16(v);
    __nv_bfloat16 lo = __float2bfloat16(v - __bfloat162float(hi));
    int off = gc * WCHUNK_BYTES + m * WSTRIDE + kkl * 2;
    *reinterpret_cast<__nv_bfloat16*>(g_Whi + off) = hi;
    *reinterpret_cast<__nv_bfloat16*>(g_Wlo + off) = lo;
}

// ---------------- stage one 48k W chunk (hi+lo = 28672B = 1792 x 16B) ----------------
__device__ __forceinline__ void stage_w(uint32_t sb, int t, int gc, int buf) {
#pragma unroll
    for (int i = 0; i < 4; ++i) {
        int idx2 = t + i * NTHREADS;            // 0..2047, valid < 1792
        if (idx2 < 1792) {
            int half = idx2 >= 896;
            int off16 = (idx2 - half * 896) * 16;
            const unsigned char* gsrc = (half ? g_Wlo : g_Whi) + gc * WCHUNK_BYTES + off16;
            uint32_t sdst = sb + OFF_W + buf * WBUF_BYTES + half * WCHUNK_BYTES + off16;
            cp16(sdst, gsrc);
        }
    }
    CP_COMMIT();
}

// transform one (channel, pixel): 9 linear combos, sort 8 non-center, out9
__device__ __forceinline__ void transform_one(const float* __restrict__ xr, int nn,
                                              const float* __restrict__ cf, float* out9) {
    float v0 = xr[nn],          v1 = xr[nn + 1],          v2 = xr[nn + 2];
    float v3 = xr[XR + nn],     v4 = xr[XR + nn + 1],     v5 = xr[XR + nn + 2];
    float v6 = xr[2 * XR + nn], v7 = xr[2 * XR + nn + 1], v8 = xr[2 * XR + nn + 2];
    float yv[8];
#pragma unroll
    for (int q = 0; q < 8; ++q) {
        int ri = q + (q >= 4 ? 1 : 0);
        const float* cr = &cf[ri * 9];
        float s = cr[0] * v0;
        s = fmaf(cr[1], v1, s); s = fmaf(cr[2], v2, s);
        s = fmaf(cr[3], v3, s); s = fmaf(cr[4], v4, s);
        s = fmaf(cr[5], v5, s); s = fmaf(cr[6], v6, s);
        s = fmaf(cr[7], v7, s); s = fmaf(cr[8], v8, s);
        yv[q] = s;
    }
#define CS(a, bb) { float _l = fminf(yv[a], yv[bb]); float _h = fmaxf(yv[a], yv[bb]); yv[a] = _l; yv[bb] = _h; }
    CS(0,1) CS(2,3) CS(4,5) CS(6,7)
    CS(0,2) CS(1,3) CS(4,6) CS(5,7)
    CS(1,2) CS(5,6)
    CS(0,4) CS(1,5) CS(2,6) CS(3,7)
    CS(2,4) CS(3,5)
    CS(1,2) CS(3,4) CS(5,6)
#undef CS
    out9[0] = yv[0]; out9[1] = yv[1]; out9[2] = yv[2]; out9[3] = yv[3];
    out9[4] = v4;
    out9[5] = yv[4]; out9[6] = yv[5]; out9[7] = yv[6]; out9[8] = yv[7];
}

// ---------------- main fused kernel ----------------
__global__ __launch_bounds__(NTHREADS, 1)
void sconv_mma_kernel(const float* __restrict__ xg,
                      const float* __restrict__ coefg,
                      const float* __restrict__ biasg,
                      float* __restrict__ outg) {
    extern __shared__ __align__(1024) unsigned char smem[];
    const uint32_t sb = smem_u32(smem);
    const int t   = threadIdx.x;
    const int wid = t >> 5;
    const int lid = t & 31;
    const int b   = blockIdx.z;
    const int h   = blockIdx.y;

    float* cf = reinterpret_cast<float*>(smem + OFF_CF);
    float* xs = reinterpret_cast<float*>(smem + OFF_XS);

    if (t < 81) cf[t] = coefg[t];

    // warp tiling: 4 n-tiles (32 px) x 4 m-tiles (32 ch)
    const int nt = wid & 3;
    const int mq = wid >> 2;
    const int n0 = nt * 32;
    const int mbase = mq * 32;

    float acc[2][4][4];
#pragma unroll
    for (int i = 0; i < 2; ++i)
#pragma unroll
        for (int j = 0; j < 4; ++j)
#pragma unroll
            for (int q = 0; q < 4; ++q) acc[i][j][q] = 0.0f;

    // A (z) ldmatrix x4 addressing: 16n x 16k tiles
    const int rA   = lid & 7;
    const int matA = lid >> 3;
    const uint32_t aBase = sb + OFF_ZHI +
        (uint32_t)(n0 + rA + ((matA & 1) << 3)) * ZSTRIDE + (((matA >> 1) << 3) << 1);
    // B (W) ldmatrix x4 addressing: 16k x 16m tiles
    const int gB = lid >> 3;
    const int rB = lid & 7;
    const uint32_t bOff = (uint32_t)(mbase + (((gB & 2) << 2)) + rB) * WSTRIDE + ((gB & 1) << 4);

    // transform lane roles: lane = cpair(0..15) + 16*sub
    const int sub = lid >> 4;
    const int cp  = lid & 15;

    for (int cc = 0; cc < 2; ++cc) {
        __syncthreads();   // region (xs/W) free: prior GEMM half fully done

        // ---- stage x chunk: channels cc*32 .. cc*32+31, 3 rows x 131 cols each
        {
            const float* xb = xg + (((long long)b * 64 + cc * 32) << 14);
            for (int idx = t; idx < 32 * XC; idx += NTHREADS) {
                int c   = idx / XC;
                int rem = idx - c * XC;
                int r   = rem / XR;
                int col = rem - r * XR;
                int gr  = h + r - 1;
                int gcn = col - 1;
                float val = 0.0f;
                if ((unsigned)gr < 128u && (unsigned)gcn < 128u)
                    val = xb[(c << 14) + (gr << 7) + gcn];
                xs[idx] = val;
            }
        }
        __syncthreads();

        // ---- transform: channel pair (2cp, 2cp+1), pixel nn -> 18 k values packed u32
        {
            const float* xr0 = xs + (2 * cp) * XC;
            const float* xr1 = xr0 + XC;
#pragma unroll 1
            for (int it = 0; it < 4; ++it) {
                int nn = wid * 8 + it * 2 + sub;
                float s18[18];
                transform_one(xr0, nn, cf, s18);
                transform_one(xr1, nn, cf, s18 + 9);
                uint32_t hw[9], lw[9];
#pragma unroll
                for (int j = 0; j < 9; ++j) {
                    float a = s18[2 * j], c2 = s18[2 * j + 1];
                    __nv_bfloat16 ha = __float2bfloat16(a);
                    __nv_bfloat16 hb = __float2bfloat16(c2);
                    __nv_bfloat16 la = __float2bfloat16(a - __bfloat162float(ha));
                    __nv_bfloat16 lb = __float2bfloat16(c2 - __bfloat162float(hb));
                    hw[j] = (uint32_t)__bfloat16_as_ushort(ha) |
                            ((uint32_t)__bfloat16_as_ushort(hb) << 16);
                    lw[j] = (uint32_t)__bfloat16_as_ushort(la) |
                            ((uint32_t)__bfloat16_as_ushort(lb) << 16);
                }
                uint32_t* zh = reinterpret_cast<uint32_t*>(smem + OFF_ZHI + nn * ZSTRIDE + cp * 36);
                uint32_t* zl = reinterpret_cast<uint32_t*>(smem + OFF_ZLO + nn * ZSTRIDE + cp * 36);
#pragma unroll
                for (int j = 0; j < 9; ++j) { zh[j] = hw[j]; zl[j] = lw[j]; }
            }
        }
        __syncthreads();   // z ready; xs no longer needed -> W buffers may use region

        // ---- GEMM half: 6 W chunks of 48k, double-buffered
        stage_w(sb, t, cc * 6, 0);
        for (int wc = 0; wc < 6; ++wc) {
            int buf = wc & 1;
            CP_WAIT0();
            __syncthreads();
            if (wc < 5) stage_w(sb, t, cc * 6 + wc + 1, buf ^ 1);

            const uint32_t wB = sb + OFF_W + buf * WBUF_BYTES + bOff;
#pragma unroll
            for (int ks = 0; ks < 3; ++ks) {
                uint32_t aAddr = aBase + (uint32_t)(wc * 48 + ks * 16) * 2;
                uint32_t ahi[2][4], alo[2][4];
                ldm_x4(ahi[0], aAddr);
                ldm_x4(ahi[1], aAddr + 16 * ZSTRIDE);
                ldm_x4(alo[0], aAddr + (OFF_ZLO - OFF_ZHI));
                ldm_x4(alo[1], aAddr + (OFF_ZLO - OFF_ZHI) + 16 * ZSTRIDE);
#pragma unroll
                for (int p = 0; p < 2; ++p) {
                    uint32_t bAddr = wB + p * (16 * WSTRIDE) + ks * 32;
                    uint32_t bhi[4], blo[4];
                    ldm_x4(bhi, bAddr);
                    ldm_x4(blo, bAddr + WCHUNK_BYTES);
#pragma unroll
                    for (int nb = 0; nb < 2; ++nb) {
                        mma16816(acc[nb][2 * p],     ahi[nb], bhi);
                        mma16816(acc[nb][2 * p],     ahi[nb], blo);
                        mma16816(acc[nb][2 * p],     alo[nb], bhi);
                        mma16816(acc[nb][2 * p + 1], ahi[nb], bhi + 2);
                        mma16816(acc[nb][2 * p + 1], ahi[nb], blo + 2);
                        mma16816(acc[nb][2 * p + 1], alo[nb], bhi + 2);
                    }
                }
            }
        }
    }

    // ---- epilogue: two 64-pixel passes through smem transpose buffer
    float* ob = reinterpret_cast<float*>(smem + OFF_OB);
    const long long obase0 = (((long long)b * 128) * 128 + h) * 128;
#pragma unroll 1
    for (int e = 0; e < 2; ++e) {
        __syncthreads();   // ob region free (W reads / previous pass reads done)
        if ((nt >> 1) == e) {
            int mc0 = mbase + ((lid & 3) << 1);
#pragma unroll
            for (int nb = 0; nb < 2; ++nb) {
                int r0 = n0 - 64 * e + 16 * nb + (lid >> 2);
#pragma unroll
                for (int mb = 0; mb < 4; ++mb) {
                    int mc = mc0 + mb * 8;
                    ob[r0 * 129 + mc]           = acc[nb][mb][0];
                    ob[r0 * 129 + mc + 1]       = acc[nb][mb][1];
                    ob[(r0 + 8) * 129 + mc]     = acc[nb][mb][2];
                    ob[(r0 + 8) * 129 + mc + 1] = acc[nb][mb][3];
                }
            }
        }
        __syncthreads();
#pragma unroll
        for (int it = 0; it < 4; ++it) {
            int m = it * 32 + (t >> 4);
            int g = t & 15;
            float bv = __ldg(biasg + m);
            int n0s = 4 * g;
            float4 o;
            o.x = ob[(n0s + 0) * 129 + m] + bv;
            o.y = ob[(n0s + 1) * 129 + m] + bv;
            o.z = ob[(n0s + 2) * 129 + m] + bv;
            o.w = ob[(n0s + 3) * 129 + m] + bv;
            *reinterpret_cast<float4*>(outg + obase0 + ((long long)m << 14) + 64 * e + n0s) = o;
        }
    }
}

extern "C" void kernel_launch(void* const* d_in, const int* in_sizes, int n_in,
                              void* d_out, int out_size) {
    const float *x = nullptr, *coef = nullptr, *w = nullptr, *bias = nullptr;
    for (int i = 0; i < n_in; ++i) {
        switch (in_sizes[i]) {
            case 8388608: x    = (const float*)d_in[i]; break;
            case 81:      coef = (const float*)d_in[i]; break;
            case 73728:   w    = (const float*)d_in[i]; break;
            case 128:     bias = (const float*)d_in[i]; break;
        }
    }
    presplit_w<<<72, 1024>>>(w);
    cudaFuncSetAttribute(sconv_mma_kernel,
                         cudaFuncAttributeMaxDynamicSharedMemorySize, SMEM_BYTES);
    dim3 grid(1, 128, 8);
    sconv_mma_kernel<<<grid, NTHREADS, SMEM_BYTES>>>(x, coef, bias, (float*)d_out);
}

// round 9
// speedup vs baseline: 3.0566x; 1.5200x over previous
#include <cuda_runtime.h>
#include <cuda_fp16.h>
#include <cstdint>

// Fused SConv via warp-level fp16 single-pass mma.sync GEMM.
// out[m=128, n] = sum_k W[m,k] * z[k,n], K=576, 128 pixels per CTA.
// fp16 operands, f32 accumulate: aggregate rel err ~4e-4 (< 1e-3).
// R9: single z buffer (full K), single W stream, 32n x 32m warp tiles.

#define NTHREADS 512
#define ZSTRIDE 1168         // 576*2 + 16 pad (conflict-free ldmatrix: 292 % 32 = 4)
#define WSTRIDE 144          // 64*2 + 16 pad  (36 % 32 = 4)
#define XC 393               // floats per channel in x stage (3 rows x 131)
#define XR 131

#define OFF_Z   0            // 128 x 1168 = 149504
#define OFF_W   149504       // 2 x 18432 W buffers = 36864
#define OFF_XS  149504       // 32*393*4 = 50304 (overlaps W; phase-separated)
#define OFF_OB  149504       // 64*129*4 = 33024 (overlaps W; after GEMM)
#define OFF_CF  199808       // 81 floats
#define SMEM_BYTES 200192

#define WCHUNK_BYTES 18432   // 128 m x 144 B (64 k values)

__device__ __align__(16) unsigned char g_Wh[9 * WCHUNK_BYTES];

__device__ __forceinline__ uint32_t smem_u32(const void* p) {
    uint32_t a;
    asm("{ .reg .u64 t; cvta.to.shared.u64 t, %1; cvt.u32.u64 %0, t; }" : "=r"(a) : "l"(p));
    return a;
}
__device__ __forceinline__ void ldm_x4(uint32_t* r, uint32_t addr) {
    asm volatile("ldmatrix.sync.aligned.m8n8.x4.shared.b16 {%0,%1,%2,%3}, [%4];"
                 : "=r"(r[0]), "=r"(r[1]), "=r"(r[2]), "=r"(r[3]) : "r"(addr));
}
__device__ __forceinline__ void mma16816(float* d, const uint32_t* a, const uint32_t* b) {
    asm volatile("mma.sync.aligned.m16n8k16.row.col.f32.f16.f16.f32 "
                 "{%0,%1,%2,%3}, {%4,%5,%6,%7}, {%8,%9}, {%0,%1,%2,%3};"
                 : "+f"(d[0]), "+f"(d[1]), "+f"(d[2]), "+f"(d[3])
                 : "r"(a[0]), "r"(a[1]), "r"(a[2]), "r"(a[3]), "r"(b[0]), "r"(b[1]));
}
__device__ __forceinline__ void cp16(uint32_t saddr, const void* gaddr) {
    asm volatile("cp.async.ca.shared.global [%0], [%1], 16;" :: "r"(saddr), "l"(gaddr));
}
#define CP_COMMIT() asm volatile("cp.async.commit_group;" ::: "memory")
#define CP_WAIT0()  asm volatile("cp.async.wait_group 0;" ::: "memory")

// ---------------- W pre-convert: fp16 chunks [9][m 128][64k], 144B rows ----------------
__global__ void presplit_w(const float* __restrict__ wg) {
    int idx = blockIdx.x * blockDim.x + threadIdx.x;   // 73728
    int m  = idx / 576;
    int kk = idx - m * 576;
    int ch  = kk >> 6;
    int kl  = kk & 63;
    float v = wg[m * 576 + kk];
    int off = ch * WCHUNK_BYTES + m * WSTRIDE + kl * 2;
    *reinterpret_cast<__half*>(g_Wh + off) = __float2half_rn(v);
}

// ---------------- stage one 64k W chunk (18432B = 1152 x 16B) ----------------
__device__ __forceinline__ void stage_w(uint32_t sb, int t, int ch, int buf) {
#pragma unroll
    for (int i = 0; i < 3; ++i) {
        int idx2 = t + i * NTHREADS;            // 0..1535, valid < 1152
        if (idx2 < 1152) {
            int off16 = idx2 * 16;
            cp16(sb + OFF_W + buf * WCHUNK_BYTES + off16,
                 g_Wh + ch * WCHUNK_BYTES + off16);
        }
    }
    CP_COMMIT();
}

// transform one (channel, pixel): 9 linear combos, sort 8 non-center, out9
__device__ __forceinline__ void transform_one(const float* __restrict__ xr, int nn,
                                              const float* __restrict__ cf, float* out9) {
    float v0 = xr[nn],          v1 = xr[nn + 1],          v2 = xr[nn + 2];
    float v3 = xr[XR + nn],     v4 = xr[XR + nn + 1],     v5 = xr[XR + nn + 2];
    float v6 = xr[2 * XR + nn], v7 = xr[2 * XR + nn + 1], v8 = xr[2 * XR + nn + 2];
    float yv[8];
#pragma unroll
    for (int q = 0; q < 8; ++q) {
        int ri = q + (q >= 4 ? 1 : 0);
        const float* cr = &cf[ri * 9];
        float s = cr[0] * v0;
        s = fmaf(cr[1], v1, s); s = fmaf(cr[2], v2, s);
        s = fmaf(cr[3], v3, s); s = fmaf(cr[4], v4, s);
        s = fmaf(cr[5], v5, s); s = fmaf(cr[6], v6, s);
        s = fmaf(cr[7], v7, s); s = fmaf(cr[8], v8, s);
        yv[q] = s;
    }
#define CS(a, bb) { float _l = fminf(yv[a], yv[bb]); float _h = fmaxf(yv[a], yv[bb]); yv[a] = _l; yv[bb] = _h; }
    CS(0,1) CS(2,3) CS(4,5) CS(6,7)
    CS(0,2) CS(1,3) CS(4,6) CS(5,7)
    CS(1,2) CS(5,6)
    CS(0,4) CS(1,5) CS(2,6) CS(3,7)
    CS(2,4) CS(3,5)
    CS(1,2) CS(3,4) CS(5,6)
#undef CS
    out9[0] = yv[0]; out9[1] = yv[1]; out9[2] = yv[2]; out9[3] = yv[3];
    out9[4] = v4;
    out9[5] = yv[4]; out9[6] = yv[5]; out9[7] = yv[6]; out9[8] = yv[7];
}

// ---------------- main fused kernel ----------------
__global__ __launch_bounds__(NTHREADS, 1)
void sconv_mma_kernel(const float* __restrict__ xg,
                      const float* __restrict__ coefg,
                      const float* __restrict__ biasg,
                      float* __restrict__ outg) {
    extern __shared__ __align__(1024) unsigned char smem[];
    const uint32_t sb = smem_u32(smem);
    const int t   = threadIdx.x;
    const int wid = t >> 5;
    const int lid = t & 31;
    const int b   = blockIdx.z;
    const int h   = blockIdx.y;

    float* cf = reinterpret_cast<float*>(smem + OFF_CF);
    float* xs = reinterpret_cast<float*>(smem + OFF_XS);

    if (t < 81) cf[t] = coefg[t];

    // warp tiling: 4 n-tiles (32 px) x 4 m-tiles (32 ch)
    const int nt = wid & 3;
    const int mq = wid >> 2;
    const int n0 = nt * 32;
    const int mbase = mq * 32;

    float acc[2][4][4];
#pragma unroll
    for (int i = 0; i < 2; ++i)
#pragma unroll
        for (int j = 0; j < 4; ++j)
#pragma unroll
            for (int q = 0; q < 4; ++q) acc[i][j][q] = 0.0f;

    // A (z) ldmatrix x4 addressing: 16n x 16k tiles
    const int rA   = lid & 7;
    const int matA = lid >> 3;
    const uint32_t aBase = sb + OFF_Z +
        (uint32_t)(n0 + rA + ((matA & 1) << 3)) * ZSTRIDE + (((matA >> 1) << 3) << 1);
    // B (W) ldmatrix x4 addressing: 16k x 16m tiles
    const int gB = lid >> 3;
    const int rB = lid & 7;
    const uint32_t bOff = (uint32_t)(mbase + ((gB & 2) << 2) + rB) * WSTRIDE + ((gB & 1) << 4);

    // transform lane roles
    const int sub = lid >> 4;
    const int cp  = lid & 15;

    // ---- build full z (K=576) in two 32-channel phases (x stage reuse)
    for (int cc = 0; cc < 2; ++cc) {
        __syncthreads();   // xs free (prev transform reads done / first pass)

        {
            const float* xb = xg + (((long long)b * 64 + cc * 32) << 14);
            for (int idx = t; idx < 32 * XC; idx += NTHREADS) {
                int c   = idx / XC;
                int rem = idx - c * XC;
                int r   = rem / XR;
                int col = rem - r * XR;
                int gr  = h + r - 1;
                int gcn = col - 1;
                float val = 0.0f;
                if ((unsigned)gr < 128u && (unsigned)gcn < 128u)
                    val = xb[(c << 14) + (gr << 7) + gcn];
                xs[idx] = val;
            }
        }
        __syncthreads();

        const float* xr0 = xs + (2 * cp) * XC;
        const float* xr1 = xr0 + XC;
        const uint32_t zcol = (uint32_t)(cc * 32 + 2 * cp) * 18;   // byte offset of k base
#pragma unroll 1
        for (int it = 0; it < 4; ++it) {
            int nn = wid * 8 + it * 2 + sub;
            float s18[18];
            transform_one(xr0, nn, cf, s18);
            transform_one(xr1, nn, cf, s18 + 9);
            uint32_t hw[9];
#pragma unroll
            for (int j = 0; j < 9; ++j) {
                __half a = __float2half_rn(s18[2 * j]);
                __half c2 = __float2half_rn(s18[2 * j + 1]);
                hw[j] = (uint32_t)__half_as_ushort(a) |
                        ((uint32_t)__half_as_ushort(c2) << 16);
            }
            uint32_t* zh = reinterpret_cast<uint32_t*>(smem + OFF_Z + nn * ZSTRIDE + zcol);
#pragma unroll
            for (int j = 0; j < 9; ++j) zh[j] = hw[j];
        }
    }

    // xs aliases W buffers: all transform reads must complete before staging.
    __syncthreads();
    stage_w(sb, t, 0, 0);

    // ---- GEMM: 9 chunks of 64k, W double-buffered
    for (int ch = 0; ch < 9; ++ch) {
        int buf = ch & 1;
        CP_WAIT0();
        __syncthreads();
        if (ch < 8) stage_w(sb, t, ch + 1, buf ^ 1);

        const uint32_t wB = sb + OFF_W + buf * WCHUNK_BYTES + bOff;
#pragma unroll
        for (int ks = 0; ks < 4; ++ks) {
            uint32_t aAddr = aBase + (uint32_t)(ch * 64 + ks * 16) * 2;
            uint32_t a0[4], a1[4];
            ldm_x4(a0, aAddr);
            ldm_x4(a1, aAddr + 16 * ZSTRIDE);
#pragma unroll
            for (int p = 0; p < 2; ++p) {
                uint32_t bb[4];
                ldm_x4(bb, wB + p * (16 * WSTRIDE) + ks * 32);
                mma16816(acc[0][2 * p],     a0, bb);
                mma16816(acc[0][2 * p + 1], a0, bb + 2);
                mma16816(acc[1][2 * p],     a1, bb);
                mma16816(acc[1][2 * p + 1], a1, bb + 2);
            }
        }
    }

    // ---- epilogue: two 64-pixel passes through smem transpose buffer
    float* ob = reinterpret_cast<float*>(smem + OFF_OB);
    const long long obase0 = (((long long)b * 128) * 128 + h) * 128;
#pragma unroll 1
    for (int e = 0; e < 2; ++e) {
        __syncthreads();   // ob region free
        if ((nt >> 1) == e) {
            int mc0 = mbase + ((lid & 3) << 1);
#pragma unroll
            for (int nb = 0; nb < 2; ++nb) {
                int r0 = n0 - 64 * e + 16 * nb + (lid >> 2);
#pragma unroll
                for (int mb = 0; mb < 4; ++mb) {
                    int mc = mc0 + mb * 8;
                    ob[r0 * 129 + mc]           = acc[nb][mb][0];
                    ob[r0 * 129 + mc + 1]       = acc[nb][mb][1];
                    ob[(r0 + 8) * 129 + mc]     = acc[nb][mb][2];
                    ob[(r0 + 8) * 129 + mc + 1] = acc[nb][mb][3];
                }
            }
        }
        __syncthreads();
#pragma unroll
        for (int it = 0; it < 4; ++it) {
            int m = it * 32 + (t >> 4);
            int g = t & 15;
            float bv = __ldg(biasg + m);
            int n0s = 4 * g;
            float4 o;
            o.x = ob[(n0s + 0) * 129 + m] + bv;
            o.y = ob[(n0s + 1) * 129 + m] + bv;
            o.z = ob[(n0s + 2) * 129 + m] + bv;
            o.w = ob[(n0s + 3) * 129 + m] + bv;
            *reinterpret_cast<float4*>(outg + obase0 + ((long long)m << 14) + 64 * e + n0s) = o;
        }
    }
}

extern "C" void kernel_launch(void* const* d_in, const int* in_sizes, int n_in,
                              void* d_out, int out_size) {
    const float *x = nullptr, *coef = nullptr, *w = nullptr, *bias = nullptr;
    for (int i = 0; i < n_in; ++i) {
        switch (in_sizes[i]) {
            case 8388608: x    = (const float*)d_in[i]; break;
            case 81:      coef = (const float*)d_in[i]; break;
            case 73728:   w    = (const float*)d_in[i]; break;
            case 128:     bias = (const float*)d_in[i]; break;
        }
    }
    presplit_w<<<72, 1024>>>(w);
    cudaFuncSetAttribute(sconv_mma_kernel,
                         cudaFuncAttributeMaxDynamicSharedMemorySize, SMEM_BYTES);
    dim3 grid(1, 128, 8);
    sconv_mma_kernel<<<grid, NTHREADS, SMEM_BYTES>>>(x, coef, bias, (float*)d_out);
}

// round 11
// speedup vs baseline: 3.4328x; 1.1231x over previous
#include <cuda_runtime.h>
#include <cuda_fp16.h>
#include <cstdint>

// Fused SConv via warp-level fp16 mma.sync GEMM.
// out[m=128, n] = sum_k W[m,k] * z[k,n], K=576, 64 pixels per CTA.
// R11: R10 layout (2 CTAs/SM, 112KB smem, 16n x 32m warp tiles) with the
//      transform k-packing fixed back to consecutive-k (R9 semantics).

#define NTHREADS 512
#define ZSTRIDE 1168         // 576*2 + 16 pad (ldmatrix conflict-free)
#define WSTRIDE 144          // 64*2 + 16 pad
#define XC 201               // floats per channel in x stage (3 rows x 67)
#define XR 67

#define OFF_Z   0            // 64 x 1168 = 74752
#define OFF_W   74752        // 2 x 18432 W buffers = 36864
#define OFF_XS  74752        // 32*201*4 = 25728 (overlaps W; phase-separated)
#define OFF_OB  74752        // 64*129*4 = 33024 (overlaps W; after GEMM)
#define OFF_CF  111616       // 81 floats
#define SMEM_BYTES 112000

#define WCHUNK_BYTES 18432   // 128 m x 144 B (64 k values)

__device__ __align__(16) unsigned char g_Wh[9 * WCHUNK_BYTES];

__device__ __forceinline__ uint32_t smem_u32(const void* p) {
    uint32_t a;
    asm("{ .reg .u64 t; cvta.to.shared.u64 t, %1; cvt.u32.u64 %0, t; }" : "=r"(a) : "l"(p));
    return a;
}
__device__ __forceinline__ void ldm_x4(uint32_t* r, uint32_t addr) {
    asm volatile("ldmatrix.sync.aligned.m8n8.x4.shared.b16 {%0,%1,%2,%3}, [%4];"
                 : "=r"(r[0]), "=r"(r[1]), "=r"(r[2]), "=r"(r[3]) : "r"(addr));
}
__device__ __forceinline__ void mma16816(float* d, const uint32_t* a, const uint32_t* b) {
    asm volatile("mma.sync.aligned.m16n8k16.row.col.f32.f16.f16.f32 "
                 "{%0,%1,%2,%3}, {%4,%5,%6,%7}, {%8,%9}, {%0,%1,%2,%3};"
                 : "+f"(d[0]), "+f"(d[1]), "+f"(d[2]), "+f"(d[3])
                 : "r"(a[0]), "r"(a[1]), "r"(a[2]), "r"(a[3]), "r"(b[0]), "r"(b[1]));
}
__device__ __forceinline__ void cp16(uint32_t saddr, const void* gaddr) {
    asm volatile("cp.async.ca.shared.global [%0], [%1], 16;" :: "r"(saddr), "l"(gaddr));
}
#define CP_COMMIT() asm volatile("cp.async.commit_group;" ::: "memory")
#define CP_WAIT0()  asm volatile("cp.async.wait_group 0;" ::: "memory")

// ---------------- W pre-convert: fp16 chunks [9][m 128][64k], 144B rows ----------------
__global__ void presplit_w(const float* __restrict__ wg) {
    int idx = blockIdx.x * blockDim.x + threadIdx.x;   // 73728
    int m  = idx / 576;
    int kk = idx - m * 576;
    int ch  = kk >> 6;
    int kl  = kk & 63;
    float v = wg[m * 576 + kk];
    int off = ch * WCHUNK_BYTES + m * WSTRIDE + kl * 2;
    *reinterpret_cast<__half*>(g_Wh + off) = __float2half_rn(v);
}

// ---------------- stage one 64k W chunk (18432B = 1152 x 16B) ----------------
__device__ __forceinline__ void stage_w(uint32_t sb, int t, int ch, int buf) {
#pragma unroll
    for (int i = 0; i < 3; ++i) {
        int idx2 = t + i * NTHREADS;            // valid < 1152
        if (idx2 < 1152) {
            int off16 = idx2 * 16;
            cp16(sb + OFF_W + buf * WCHUNK_BYTES + off16,
                 g_Wh + ch * WCHUNK_BYTES + off16);
        }
    }
    CP_COMMIT();
}

// transform one (channel, pixel): 9 linear combos, sort 8 non-center, out9
__device__ __forceinline__ void transform_one(const float* __restrict__ xr, int nn,
                                              const float* __restrict__ cf, float* out9) {
    float v0 = xr[nn],          v1 = xr[nn + 1],          v2 = xr[nn + 2];
    float v3 = xr[XR + nn],     v4 = xr[XR + nn + 1],     v5 = xr[XR + nn + 2];
    float v6 = xr[2 * XR + nn], v7 = xr[2 * XR + nn + 1], v8 = xr[2 * XR + nn + 2];
    float yv[8];
#pragma unroll
    for (int q = 0; q < 8; ++q) {
        int ri = q + (q >= 4 ? 1 : 0);
        const float* cr = &cf[ri * 9];
        float s = cr[0] * v0;
        s = fmaf(cr[1], v1, s); s = fmaf(cr[2], v2, s);
        s = fmaf(cr[3], v3, s); s = fmaf(cr[4], v4, s);
        s = fmaf(cr[5], v5, s); s = fmaf(cr[6], v6, s);
        s = fmaf(cr[7], v7, s); s = fmaf(cr[8], v8, s);
        yv[q] = s;
    }
#define CS(a, bb) { float _l = fminf(yv[a], yv[bb]); float _h = fmaxf(yv[a], yv[bb]); yv[a] = _l; yv[bb] = _h; }
    CS(0,1) CS(2,3) CS(4,5) CS(6,7)
    CS(0,2) CS(1,3) CS(4,6) CS(5,7)
    CS(1,2) CS(5,6)
    CS(0,4) CS(1,5) CS(2,6) CS(3,7)
    CS(2,4) CS(3,5)
    CS(1,2) CS(3,4) CS(5,6)
#undef CS
    out9[0] = yv[0]; out9[1] = yv[1]; out9[2] = yv[2]; out9[3] = yv[3];
    out9[4] = v4;
    out9[5] = yv[4]; out9[6] = yv[5]; out9[7] = yv[6]; out9[8] = yv[7];
}

// ---------------- main fused kernel ----------------
__global__ __launch_bounds__(NTHREADS, 2)
void sconv_mma_kernel(const float* __restrict__ xg,
                      const float* __restrict__ coefg,
                      const float* __restrict__ biasg,
                      float* __restrict__ outg) {
    extern __shared__ __align__(1024) unsigned char smem[];
    const uint32_t sb = smem_u32(smem);
    const int t   = threadIdx.x;
    const int wid = t >> 5;
    const int lid = t & 31;
    const int b   = blockIdx.z;
    const int h   = blockIdx.y;
    const int w0  = blockIdx.x * 64;

    float* cf = reinterpret_cast<float*>(smem + OFF_CF);
    float* xs = reinterpret_cast<float*>(smem + OFF_XS);

    if (t < 81) cf[t] = coefg[t];

    // warp tiling: 4 n-tiles (16 px) x 4 m-tiles (32 ch)
    const int nt = wid & 3;
    const int mq = wid >> 2;
    const int n0 = nt * 16;
    const int mbase = mq * 32;

    float acc[4][4];
#pragma unroll
    for (int j = 0; j < 4; ++j)
#pragma unroll
        for (int q = 0; q < 4; ++q) acc[j][q] = 0.0f;

    // A (z) ldmatrix x4 addressing: 16n x 16k tiles
    const int rA   = lid & 7;
    const int matA = lid >> 3;
    const uint32_t aBase = sb + OFF_Z +
        (uint32_t)(n0 + rA + ((matA & 1) << 3)) * ZSTRIDE + (((matA >> 1) << 3) << 1);
    // B (W) ldmatrix x4 addressing: 16k x 16m tiles
    const int gB = lid >> 3;
    const int rB = lid & 7;
    const uint32_t bOff = (uint32_t)(mbase + ((gB & 2) << 2) + rB) * WSTRIDE + ((gB & 1) << 4);

    // transform lane roles
    const int sub = lid >> 4;
    const int cp  = lid & 15;

    // ---- build full z (K=576) in two 32-channel phases (x stage reuse)
    for (int cc = 0; cc < 2; ++cc) {
        __syncthreads();   // xs region free

        // stage x: c = t>>4 (32 ch), lane = t&15 covers 67 cols x 3 rows
        {
            const float* xb = xg + (((long long)b * 64 + cc * 32) << 14);
            int c    = t >> 4;
            int lane = t & 15;
            const float* xc = xb + (c << 14);
            float* xd = xs + c * XC;
#pragma unroll
            for (int r = 0; r < 3; ++r) {
                int gr = h + r - 1;
                bool rok = (unsigned)gr < 128u;
                const float* xrow = xc + (gr << 7);
#pragma unroll
                for (int i = 0; i < 5; ++i) {
                    int col = lane + (i << 4);
                    if (col < XR) {
                        int gc = w0 + col - 1;
                        float val = (rok && (unsigned)gc < 128u) ? xrow[gc] : 0.0f;
                        xd[r * XR + col] = val;
                    }
                }
            }
        }
        __syncthreads();

        const float* xr0 = xs + (2 * cp) * XC;
        const float* xr1 = xr0 + XC;
        const uint32_t zcol = (uint32_t)(cc * 32 + 2 * cp) * 18;
#pragma unroll 1
        for (int it = 0; it < 2; ++it) {
            int nn = wid * 4 + it * 2 + sub;
            float s18[18];
            transform_one(xr0, nn, cf, s18);        // k = base + 0..8
            transform_one(xr1, nn, cf, s18 + 9);    // k = base + 9..17
            uint32_t* zh = reinterpret_cast<uint32_t*>(smem + OFF_Z + nn * ZSTRIDE + zcol);
            // pack CONSECUTIVE k pairs: word j = (k=2j, k=2j+1) within the 18-k block
#pragma unroll
            for (int j = 0; j < 9; ++j) {
                __half a  = __float2half_rn(s18[2 * j]);
                __half c2 = __float2half_rn(s18[2 * j + 1]);
                zh[j] = (uint32_t)__half_as_ushort(a) |
                        ((uint32_t)__half_as_ushort(c2) << 16);
            }
        }
    }

    // xs aliases W buffers: all transform reads must complete before staging.
    __syncthreads();
    stage_w(sb, t, 0, 0);

    // ---- GEMM: 9 chunks of 64k, W double-buffered
    for (int ch = 0; ch < 9; ++ch) {
        int buf = ch & 1;
        CP_WAIT0();
        __syncthreads();
        if (ch < 8) stage_w(sb, t, ch + 1, buf ^ 1);

        const uint32_t wB = sb + OFF_W + buf * WCHUNK_BYTES + bOff;
#pragma unroll
        for (int ks = 0; ks < 4; ++ks) {
            uint32_t aAddr = aBase + (uint32_t)(ch * 64 + ks * 16) * 2;
            uint32_t a0[4];
            ldm_x4(a0, aAddr);
#pragma unroll
            for (int p = 0; p < 2; ++p) {
                uint32_t bb[4];
                ldm_x4(bb, wB + p * (16 * WSTRIDE) + ks * 32);
                mma16816(acc[2 * p],     a0, bb);
                mma16816(acc[2 * p + 1], a0, bb + 2);
            }
        }
    }
    __syncthreads();   // mma done; W region -> epilogue buffer

    // ---- epilogue: fragments -> smem [n 64][129] f32 -> coalesced float4 stores
    float* ob = reinterpret_cast<float*>(smem + OFF_OB);
    {
        int r0 = n0 + (lid >> 2);
        int mc0 = mbase + ((lid & 3) << 1);
#pragma unroll
        for (int mb = 0; mb < 4; ++mb) {
            int mc = mc0 + mb * 8;
            ob[r0 * 129 + mc]           = acc[mb][0];
            ob[r0 * 129 + mc + 1]       = acc[mb][1];
            ob[(r0 + 8) * 129 + mc]     = acc[mb][2];
            ob[(r0 + 8) * 129 + mc + 1] = acc[mb][3];
        }
    }
    __syncthreads();

    const long long obase0 = (((long long)b * 128) * 128 + h) * 128 + w0;
#pragma unroll
    for (int it = 0; it < 4; ++it) {
        int m = it * 32 + (t >> 4);
        int g = t & 15;
        float bv = __ldg(biasg + m);
        int n0s = 4 * g;
        float4 o;
        o.x = ob[(n0s + 0) * 129 + m] + bv;
        o.y = ob[(n0s + 1) * 129 + m] + bv;
        o.z = ob[(n0s + 2) * 129 + m] + bv;
        o.w = ob[(n0s + 3) * 129 + m] + bv;
        *reinterpret_cast<float4*>(outg + obase0 + ((long long)m << 14) + n0s) = o;
    }
}

extern "C" void kernel_launch(void* const* d_in, const int* in_sizes, int n_in,
                              void* d_out, int out_size) {
    const float *x = nullptr, *coef = nullptr, *w = nullptr, *bias = nullptr;
    for (int i = 0; i < n_in; ++i) {
        switch (in_sizes[i]) {
            case 8388608: x    = (const float*)d_in[i]; break;
            case 81:      coef = (const float*)d_in[i]; break;
            case 73728:   w    = (const float*)d_in[i]; break;
            case 128:     bias = (const float*)d_in[i]; break;
        }
    }
    presplit_w<<<72, 1024>>>(w);
    cudaFuncSetAttribute(sconv_mma_kernel,
                         cudaFuncAttributeMaxDynamicSharedMemorySize, SMEM_BYTES);
    dim3 grid(2, 128, 8);
    sconv_mma_kernel<<<grid, NTHREADS, SMEM_BYTES>>>(x, coef, bias, (float*)d_out);
}

// round 12
// speedup vs baseline: 3.7299x; 1.0866x over previous
#include <cuda_runtime.h>
#include <cuda_fp16.h>
#include <cstdint>

// Fused SConv via warp-level fp16 mma.sync GEMM.
// out[m=128, n] = sum_k W[m,k] * z[k,n], K=576, 64 pixels per CTA.
// R12: 256-thread CTAs, 2 CTAs/SM, 8 warps of 32n x 32m tiles
//      (halves redundant B ldmatrix traffic; 128 regs/thread headroom).

#define NTHREADS 256
#define ZSTRIDE 1168         // 576*2 + 16 pad (ldmatrix conflict-free)
#define WSTRIDE 144          // 64*2 + 16 pad
#define XC 201               // floats per channel in x stage (3 rows x 67)
#define XR 67

#define OFF_Z   0            // 64 x 1168 = 74752
#define OFF_W   74752        // 2 x 18432 W buffers = 36864
#define OFF_XS  74752        // 32*201*4 = 25728 (overlaps W; phase-separated)
#define OFF_OB  74752        // 64*129*4 = 33024 (overlaps W; after GEMM)
#define OFF_CF  111616       // 81 floats
#define SMEM_BYTES 112000

#define WCHUNK_BYTES 18432   // 128 m x 144 B (64 k values)

__device__ __align__(16) unsigned char g_Wh[9 * WCHUNK_BYTES];

__device__ __forceinline__ uint32_t smem_u32(const void* p) {
    uint32_t a;
    asm("{ .reg .u64 t; cvta.to.shared.u64 t, %1; cvt.u32.u64 %0, t; }" : "=r"(a) : "l"(p));
    return a;
}
__device__ __forceinline__ void ldm_x4(uint32_t* r, uint32_t addr) {
    asm volatile("ldmatrix.sync.aligned.m8n8.x4.shared.b16 {%0,%1,%2,%3}, [%4];"
                 : "=r"(r[0]), "=r"(r[1]), "=r"(r[2]), "=r"(r[3]) : "r"(addr));
}
__device__ __forceinline__ void mma16816(float* d, const uint32_t* a, const uint32_t* b) {
    asm volatile("mma.sync.aligned.m16n8k16.row.col.f32.f16.f16.f32 "
                 "{%0,%1,%2,%3}, {%4,%5,%6,%7}, {%8,%9}, {%0,%1,%2,%3};"
                 : "+f"(d[0]), "+f"(d[1]), "+f"(d[2]), "+f"(d[3])
                 : "r"(a[0]), "r"(a[1]), "r"(a[2]), "r"(a[3]), "r"(b[0]), "r"(b[1]));
}
__device__ __forceinline__ void cp16(uint32_t saddr, const void* gaddr) {
    asm volatile("cp.async.ca.shared.global [%0], [%1], 16;" :: "r"(saddr), "l"(gaddr));
}
#define CP_COMMIT() asm volatile("cp.async.commit_group;" ::: "memory")
#define CP_WAIT0()  asm volatile("cp.async.wait_group 0;" ::: "memory")

// ---------------- W pre-convert: fp16 chunks [9][m 128][64k], 144B rows ----------------
__global__ void presplit_w(const float* __restrict__ wg) {
    int idx = blockIdx.x * blockDim.x + threadIdx.x;   // 73728
    int m  = idx / 576;
    int kk = idx - m * 576;
    int ch  = kk >> 6;
    int kl  = kk & 63;
    float v = wg[m * 576 + kk];
    int off = ch * WCHUNK_BYTES + m * WSTRIDE + kl * 2;
    *reinterpret_cast<__half*>(g_Wh + off) = __float2half_rn(v);
}

// ---------------- stage one 64k W chunk (18432B = 1152 x 16B) ----------------
__device__ __forceinline__ void stage_w(uint32_t sb, int t, int ch, int buf) {
#pragma unroll
    for (int i = 0; i < 5; ++i) {
        int idx2 = t + i * NTHREADS;            // valid < 1152
        if (idx2 < 1152) {
            int off16 = idx2 * 16;
            cp16(sb + OFF_W + buf * WCHUNK_BYTES + off16,
                 g_Wh + ch * WCHUNK_BYTES + off16);
        }
    }
    CP_COMMIT();
}

// transform one (channel, pixel): 9 linear combos, sort 8 non-center, out9
__device__ __forceinline__ void transform_one(const float* __restrict__ xr, int nn,
                                              const float* __restrict__ cf, float* out9) {
    float v0 = xr[nn],          v1 = xr[nn + 1],          v2 = xr[nn + 2];
    float v3 = xr[XR + nn],     v4 = xr[XR + nn + 1],     v5 = xr[XR + nn + 2];
    float v6 = xr[2 * XR + nn], v7 = xr[2 * XR + nn + 1], v8 = xr[2 * XR + nn + 2];
    float yv[8];
#pragma unroll
    for (int q = 0; q < 8; ++q) {
        int ri = q + (q >= 4 ? 1 : 0);
        const float* cr = &cf[ri * 9];
        float s = cr[0] * v0;
        s = fmaf(cr[1], v1, s); s = fmaf(cr[2], v2, s);
        s = fmaf(cr[3], v3, s); s = fmaf(cr[4], v4, s);
        s = fmaf(cr[5], v5, s); s = fmaf(cr[6], v6, s);
        s = fmaf(cr[7], v7, s); s = fmaf(cr[8], v8, s);
        yv[q] = s;
    }
#define CS(a, bb) { float _l = fminf(yv[a], yv[bb]); float _h = fmaxf(yv[a], yv[bb]); yv[a] = _l; yv[bb] = _h; }
    CS(0,1) CS(2,3) CS(4,5) CS(6,7)
    CS(0,2) CS(1,3) CS(4,6) CS(5,7)
    CS(1,2) CS(5,6)
    CS(0,4) CS(1,5) CS(2,6) CS(3,7)
    CS(2,4) CS(3,5)
    CS(1,2) CS(3,4) CS(5,6)
#undef CS
    out9[0] = yv[0]; out9[1] = yv[1]; out9[2] = yv[2]; out9[3] = yv[3];
    out9[4] = v4;
    out9[5] = yv[4]; out9[6] = yv[5]; out9[7] = yv[6]; out9[8] = yv[7];
}

// ---------------- main fused kernel ----------------
__global__ __launch_bounds__(NTHREADS, 2)
void sconv_mma_kernel(const float* __restrict__ xg,
                      const float* __restrict__ coefg,
                      const float* __restrict__ biasg,
                      float* __restrict__ outg) {
    extern __shared__ __align__(1024) unsigned char smem[];
    const uint32_t sb = smem_u32(smem);
    const int t   = threadIdx.x;
    const int wid = t >> 5;
    const int lid = t & 31;
    const int b   = blockIdx.z;
    const int h   = blockIdx.y;
    const int w0  = blockIdx.x * 64;

    float* cf = reinterpret_cast<float*>(smem + OFF_CF);
    float* xs = reinterpret_cast<float*>(smem + OFF_XS);

    if (t < 81) cf[t] = coefg[t];

    // warp tiling: 2 n-tiles (32 px) x 4 m-tiles (32 ch)
    const int nt = wid & 1;
    const int mq = wid >> 1;
    const int n0 = nt * 32;
    const int mbase = mq * 32;

    float acc[2][4][4];
#pragma unroll
    for (int i = 0; i < 2; ++i)
#pragma unroll
        for (int j = 0; j < 4; ++j)
#pragma unroll
            for (int q = 0; q < 4; ++q) acc[i][j][q] = 0.0f;

    // A (z) ldmatrix x4 addressing: 16n x 16k tiles (nb=1 adds 16*ZSTRIDE)
    const int rA   = lid & 7;
    const int matA = lid >> 3;
    const uint32_t aBase = sb + OFF_Z +
        (uint32_t)(n0 + rA + ((matA & 1) << 3)) * ZSTRIDE + (((matA >> 1) << 3) << 1);
    // B (W) ldmatrix x4 addressing: 16k x 16m tiles
    const int gB = lid >> 3;
    const int rB = lid & 7;
    const uint32_t bOff = (uint32_t)(mbase + ((gB & 2) << 2) + rB) * WSTRIDE + ((gB & 1) << 4);

    // transform lane roles
    const int sub = lid >> 4;
    const int cp  = lid & 15;

    // ---- build full z (K=576) in two 32-channel phases (x stage reuse)
    for (int cc = 0; cc < 2; ++cc) {
        __syncthreads();   // xs region free

        // stage x: c = t>>3 (32 ch), lane = t&7 covers 67 cols x 3 rows
        {
            const float* xb = xg + (((long long)b * 64 + cc * 32) << 14);
            int c    = t >> 3;
            int lane = t & 7;
            const float* xc = xb + (c << 14);
            float* xd = xs + c * XC;
#pragma unroll
            for (int r = 0; r < 3; ++r) {
                int gr = h + r - 1;
                bool rok = (unsigned)gr < 128u;
                const float* xrow = xc + (gr << 7);
#pragma unroll
                for (int i = 0; i < 9; ++i) {
                    int col = lane + (i << 3);
                    if (col < XR) {
                        int gc = w0 + col - 1;
                        float val = (rok && (unsigned)gc < 128u) ? xrow[gc] : 0.0f;
                        xd[r * XR + col] = val;
                    }
                }
            }
        }
        __syncthreads();

        const float* xr0 = xs + (2 * cp) * XC;
        const float* xr1 = xr0 + XC;
        const uint32_t zcol = (uint32_t)(cc * 32 + 2 * cp) * 18;
#pragma unroll 1
        for (int it = 0; it < 4; ++it) {
            int nn = wid * 8 + it * 2 + sub;
            float s18[18];
            transform_one(xr0, nn, cf, s18);        // k = base + 0..8
            transform_one(xr1, nn, cf, s18 + 9);    // k = base + 9..17
            uint32_t* zh = reinterpret_cast<uint32_t*>(smem + OFF_Z + nn * ZSTRIDE + zcol);
            // pack CONSECUTIVE k pairs: word j = (k=2j, k=2j+1)
#pragma unroll
            for (int j = 0; j < 9; ++j) {
                __half a  = __float2half_rn(s18[2 * j]);
                __half c2 = __float2half_rn(s18[2 * j + 1]);
                zh[j] = (uint32_t)__half_as_ushort(a) |
                        ((uint32_t)__half_as_ushort(c2) << 16);
            }
        }
    }

    // xs aliases W buffers: all transform reads must complete before staging.
    __syncthreads();
    stage_w(sb, t, 0, 0);

    // ---- GEMM: 9 chunks of 64k, W double-buffered
    for (int ch = 0; ch < 9; ++ch) {
        int buf = ch & 1;
        CP_WAIT0();
        __syncthreads();
        if (ch < 8) stage_w(sb, t, ch + 1, buf ^ 1);

        const uint32_t wB = sb + OFF_W + buf * WCHUNK_BYTES + bOff;
#pragma unroll
        for (int ks = 0; ks < 4; ++ks) {
            uint32_t aAddr = aBase + (uint32_t)(ch * 64 + ks * 16) * 2;
            uint32_t a0[4], a1[4];
            ldm_x4(a0, aAddr);
            ldm_x4(a1, aAddr + 16 * ZSTRIDE);
#pragma unroll
            for (int p = 0; p < 2; ++p) {
                uint32_t bb[4];
                ldm_x4(bb, wB + p * (16 * WSTRIDE) + ks * 32);
                mma16816(acc[0][2 * p],     a0, bb);
                mma16816(acc[0][2 * p + 1], a0, bb + 2);
                mma16816(acc[1][2 * p],     a1, bb);
                mma16816(acc[1][2 * p + 1], a1, bb + 2);
            }
        }
    }
    __syncthreads();   // mma done; W region -> epilogue buffer

    // ---- epilogue: fragments -> smem [n 64][129] f32 -> coalesced float4 stores
    float* ob = reinterpret_cast<float*>(smem + OFF_OB);
    {
        int mc0 = mbase + ((lid & 3) << 1);
#pragma unroll
        for (int nb = 0; nb < 2; ++nb) {
            int r0 = n0 + nb * 16 + (lid >> 2);
#pragma unroll
            for (int mb = 0; mb < 4; ++mb) {
                int mc = mc0 + mb * 8;
                ob[r0 * 129 + mc]           = acc[nb][mb][0];
                ob[r0 * 129 + mc + 1]       = acc[nb][mb][1];
                ob[(r0 + 8) * 129 + mc]     = acc[nb][mb][2];
                ob[(r0 + 8) * 129 + mc + 1] = acc[nb][mb][3];
            }
        }
    }
    __syncthreads();

    const long long obase0 = (((long long)b * 128) * 128 + h) * 128 + w0;
#pragma unroll
    for (int it = 0; it < 8; ++it) {
        int m = it * 16 + (t >> 4);
        int g = t & 15;
        float bv = __ldg(biasg + m);
        int n0s = 4 * g;
        float4 o;
        o.x = ob[(n0s + 0) * 129 + m] + bv;
        o.y = ob[(n0s + 1) * 129 + m] + bv;
        o.z = ob[(n0s + 2) * 129 + m] + bv;
        o.w = ob[(n0s + 3) * 129 + m] + bv;
        *reinterpret_cast<float4*>(outg + obase0 + ((long long)m << 14) + n0s) = o;
    }
}

extern "C" void kernel_launch(void* const* d_in, const int* in_sizes, int n_in,
                              void* d_out, int out_size) {
    const float *x = nullptr, *coef = nullptr, *w = nullptr, *bias = nullptr;
    for (int i = 0; i < n_in; ++i) {
        switch (in_sizes[i]) {
            case 8388608: x    = (const float*)d_in[i]; break;
            case 81:      coef = (const float*)d_in[i]; break;
            case 73728:   w    = (const float*)d_in[i]; break;
            case 128:     bias = (const float*)d_in[i]; break;
        }
    }
    presplit_w<<<72, 1024>>>(w);
    cudaFuncSetAttribute(sconv_mma_kernel,
                         cudaFuncAttributeMaxDynamicSharedMemorySize, SMEM_BYTES);
    dim3 grid(2, 128, 8);
    sconv_mma_kernel<<<grid, NTHREADS, SMEM_BYTES>>>(x, coef, bias, (float*)d_out);
}

// round 13
// speedup vs baseline: 4.3288x; 1.1606x over previous
#include <cuda_runtime.h>
#include <cuda_fp16.h>
#include <cstdint>

// Fused SConv via warp-level fp16 mma.sync GEMM.
// out[m=128, n] = sum_k W[m,k] * z[k,n], K=576, 64 pixels per CTA.
// R13: W pre-packed in GLOBAL fragment order, B frags via coalesced __ldg uint4
//      (no W smem staging, no GEMM-loop syncs). 2 CTAs/SM, 32n x 32m warp tiles.

#define NTHREADS 256
#define ZSTRIDE 1168         // 576*2 + 16 pad (ldmatrix conflict-free)
#define XC 201               // floats per channel in x stage (3 rows x 67)
#define XR 67

#define OFF_Z   0            // 64 x 1168 = 74752
#define OFF_XS  74752        // 32*201*4 = 25728
#define OFF_OB  0            // epilogue [64][129] f32 = 33024 (overlaps Z, after GEMM)
#define OFF_CF  100480       // 81 floats
#define SMEM_BYTES 100864

// W fragment buffer: [mq 4][ch 9][ks 4][p 2][lane 32] x uint4 (4 regs)
__device__ __align__(16) uint32_t g_Wfrag[4 * 9 * 4 * 2 * 32 * 4];

__device__ __forceinline__ uint32_t smem_u32(const void* p) {
    uint32_t a;
    asm("{ .reg .u64 t; cvta.to.shared.u64 t, %1; cvt.u32.u64 %0, t; }" : "=r"(a) : "l"(p));
    return a;
}
__device__ __forceinline__ void ldm_x4(uint32_t* r, uint32_t addr) {
    asm volatile("ldmatrix.sync.aligned.m8n8.x4.shared.b16 {%0,%1,%2,%3}, [%4];"
                 : "=r"(r[0]), "=r"(r[1]), "=r"(r[2]), "=r"(r[3]) : "r"(addr));
}
__device__ __forceinline__ void mma16816(float* d, const uint32_t* a,
                                         uint32_t b0, uint32_t b1) {
    asm volatile("mma.sync.aligned.m16n8k16.row.col.f32.f16.f16.f32 "
                 "{%0,%1,%2,%3}, {%4,%5,%6,%7}, {%8,%9}, {%0,%1,%2,%3};"
                 : "+f"(d[0]), "+f"(d[1]), "+f"(d[2]), "+f"(d[3])
                 : "r"(a[0]), "r"(a[1]), "r"(a[2]), "r"(a[3]), "r"(b0), "r"(b1));
}

// ---------------- W pre-pack into fragment order ----------------
// idx = ((((mq*9 + ch)*4 + ks)*2 + p)*32 + l)*4 + q
// reg q, lane l of the B fragment for tile (m = mq*32+p*16, k = ch*64+ks*16):
//   m = base_m + 8*(q>>1) + (l>>2),  k = base_k + 8*(q&1) + 2*(l&3) + {0,1}
__global__ void prepack_w(const float* __restrict__ wg) {
    int idx = blockIdx.x * blockDim.x + threadIdx.x;   // 36864
    if (idx >= 4 * 9 * 4 * 2 * 32 * 4) return;
    int q = idx & 3;  int r = idx >> 2;
    int l = r & 31;   r >>= 5;
    int p = r & 1;    r >>= 1;
    int ks = r & 3;   r >>= 2;
    int ch = r % 9;
    int mq = r / 9;
    int m = mq * 32 + p * 16 + ((q >> 1) << 3) + (l >> 2);
    int k = ch * 64 + ks * 16 + ((q & 1) << 3) + ((l & 3) << 1);
    __half h0 = __float2half_rn(wg[m * 576 + k]);
    __half h1 = __float2half_rn(wg[m * 576 + k + 1]);
    g_Wfrag[idx] = (uint32_t)__half_as_ushort(h0) |
                   ((uint32_t)__half_as_ushort(h1) << 16);
}

// transform one (channel, pixel): 9 linear combos, sort 8 non-center, out9
__device__ __forceinline__ void transform_one(const float* __restrict__ xr, int nn,
                                              const float* __restrict__ cf, float* out9) {
    float v0 = xr[nn],          v1 = xr[nn + 1],          v2 = xr[nn + 2];
    float v3 = xr[XR + nn],     v4 = xr[XR + nn + 1],     v5 = xr[XR + nn + 2];
    float v6 = xr[2 * XR + nn], v7 = xr[2 * XR + nn + 1], v8 = xr[2 * XR + nn + 2];
    float yv[8];
#pragma unroll
    for (int q = 0; q < 8; ++q) {
        int ri = q + (q >= 4 ? 1 : 0);
        const float* cr = &cf[ri * 9];
        float s = cr[0] * v0;
        s = fmaf(cr[1], v1, s); s = fmaf(cr[2], v2, s);
        s = fmaf(cr[3], v3, s); s = fmaf(cr[4], v4, s);
        s = fmaf(cr[5], v5, s); s = fmaf(cr[6], v6, s);
        s = fmaf(cr[7], v7, s); s = fmaf(cr[8], v8, s);
        yv[q] = s;
    }
#define CS(a, bb) { float _l = fminf(yv[a], yv[bb]); float _h = fmaxf(yv[a], yv[bb]); yv[a] = _l; yv[bb] = _h; }
    CS(0,1) CS(2,3) CS(4,5) CS(6,7)
    CS(0,2) CS(1,3) CS(4,6) CS(5,7)
    CS(1,2) CS(5,6)
    CS(0,4) CS(1,5) CS(2,6) CS(3,7)
    CS(2,4) CS(3,5)
    CS(1,2) CS(3,4) CS(5,6)
#undef CS
    out9[0] = yv[0]; out9[1] = yv[1]; out9[2] = yv[2]; out9[3] = yv[3];
    out9[4] = v4;
    out9[5] = yv[4]; out9[6] = yv[5]; out9[7] = yv[6]; out9[8] = yv[7];
}

// ---------------- main fused kernel ----------------
__global__ __launch_bounds__(NTHREADS, 2)
void sconv_mma_kernel(const float* __restrict__ xg,
                      const float* __restrict__ coefg,
                      const float* __restrict__ biasg,
                      float* __restrict__ outg) {
    extern __shared__ __align__(1024) unsigned char smem[];
    const uint32_t sb = smem_u32(smem);
    const int t   = threadIdx.x;
    const int wid = t >> 5;
    const int lid = t & 31;
    const int b   = blockIdx.z;
    const int h   = blockIdx.y;
    const int w0  = blockIdx.x * 64;

    float* cf = reinterpret_cast<float*>(smem + OFF_CF);
    float* xs = reinterpret_cast<float*>(smem + OFF_XS);

    if (t < 81) cf[t] = coefg[t];

    // warp tiling: 2 n-tiles (32 px) x 4 m-tiles (32 ch)
    const int nt = wid & 1;
    const int mq = wid >> 1;
    const int n0 = nt * 32;
    const int mbase = mq * 32;

    float acc[2][4][4];
#pragma unroll
    for (int i = 0; i < 2; ++i)
#pragma unroll
        for (int j = 0; j < 4; ++j)
#pragma unroll
            for (int q = 0; q < 4; ++q) acc[i][j][q] = 0.0f;

    // A (z) ldmatrix x4 addressing: 16n x 16k tiles (nb=1 adds 16*ZSTRIDE)
    const int rA   = lid & 7;
    const int matA = lid >> 3;
    const uint32_t aBase = sb + OFF_Z +
        (uint32_t)(n0 + rA + ((matA & 1) << 3)) * ZSTRIDE + (((matA >> 1) << 3) << 1);

    // B fragments from global fragment-order buffer
    const uint4* wfBase = reinterpret_cast<const uint4*>(g_Wfrag) + mq * (9 * 4 * 2 * 32) + lid;

    // transform lane roles
    const int sub = lid >> 4;
    const int cp  = lid & 15;

    // ---- build full z (K=576) in two 32-channel phases (x stage reuse)
    for (int cc = 0; cc < 2; ++cc) {
        __syncthreads();   // xs region free

        // stage x: c = t>>3 (32 ch), lane = t&7 covers 67 cols x 3 rows
        {
            const float* xb = xg + (((long long)b * 64 + cc * 32) << 14);
            int c    = t >> 3;
            int lane = t & 7;
            const float* xc = xb + (c << 14);
            float* xd = xs + c * XC;
#pragma unroll
            for (int r = 0; r < 3; ++r) {
                int gr = h + r - 1;
                bool rok = (unsigned)gr < 128u;
                const float* xrow = xc + (gr << 7);
#pragma unroll
                for (int i = 0; i < 9; ++i) {
                    int col = lane + (i << 3);
                    if (col < XR) {
                        int gc = w0 + col - 1;
                        float val = (rok && (unsigned)gc < 128u) ? xrow[gc] : 0.0f;
                        xd[r * XR + col] = val;
                    }
                }
            }
        }
        __syncthreads();

        const float* xr0 = xs + (2 * cp) * XC;
        const float* xr1 = xr0 + XC;
        const uint32_t zcol = (uint32_t)(cc * 32 + 2 * cp) * 18;
#pragma unroll 1
        for (int it = 0; it < 4; ++it) {
            int nn = wid * 8 + it * 2 + sub;
            float s18[18];
            transform_one(xr0, nn, cf, s18);        // k = base + 0..8
            transform_one(xr1, nn, cf, s18 + 9);    // k = base + 9..17
            uint32_t* zh = reinterpret_cast<uint32_t*>(smem + OFF_Z + nn * ZSTRIDE + zcol);
            // pack CONSECUTIVE k pairs: word j = (k=2j, k=2j+1)
#pragma unroll
            for (int j = 0; j < 9; ++j) {
                __half a  = __float2half_rn(s18[2 * j]);
                __half c2 = __float2half_rn(s18[2 * j + 1]);
                zh[j] = (uint32_t)__half_as_ushort(a) |
                        ((uint32_t)__half_as_ushort(c2) << 16);
            }
        }
    }
    __syncthreads();   // z ready

    // ---- GEMM: 9 chunks of 64k; B fragments straight from L2 (no syncs)
    for (int ch = 0; ch < 9; ++ch) {
        const uint4* wf = wfBase + ch * (4 * 2 * 32);
#pragma unroll
        for (int ks = 0; ks < 4; ++ks) {
            uint32_t aAddr = aBase + (uint32_t)(ch * 64 + ks * 16) * 2;
            uint32_t a0[4], a1[4];
            ldm_x4(a0, aAddr);
            ldm_x4(a1, aAddr + 16 * ZSTRIDE);
            uint4 b0 = __ldg(wf + (ks * 2 + 0) * 32);
            uint4 b1 = __ldg(wf + (ks * 2 + 1) * 32);
            mma16816(acc[0][0], a0, b0.x, b0.y);
            mma16816(acc[0][1], a0, b0.z, b0.w);
            mma16816(acc[1][0], a1, b0.x, b0.y);
            mma16816(acc[1][1], a1, b0.z, b0.w);
            mma16816(acc[0][2], a0, b1.x, b1.y);
            mma16816(acc[0][3], a0, b1.z, b1.w);
            mma16816(acc[1][2], a1, b1.x, b1.y);
            mma16816(acc[1][3], a1, b1.z, b1.w);
        }
    }
    __syncthreads();   // all z reads done; Z region -> epilogue buffer

    // ---- epilogue: fragments -> smem [n 64][129] f32 -> coalesced float4 stores
    float* ob = reinterpret_cast<float*>(smem + OFF_OB);
    {
        int mc0 = mbase + ((lid & 3) << 1);
#pragma unroll
        for (int nb = 0; nb < 2; ++nb) {
            int r0 = n0 + nb * 16 + (lid >> 2);
#pragma unroll
            for (int mb = 0; mb < 4; ++mb) {
                int mc = mc0 + mb * 8;
                ob[r0 * 129 + mc]           = acc[nb][mb][0];
                ob[r0 * 129 + mc + 1]       = acc[nb][mb][1];
                ob[(r0 + 8) * 129 + mc]     = acc[nb][mb][2];
                ob[(r0 + 8) * 129 + mc + 1] = acc[nb][mb][3];
            }
        }
    }
    __syncthreads();

    const long long obase0 = (((long long)b * 128) * 128 + h) * 128 + w0;
#pragma unroll
    for (int it = 0; it < 8; ++it) {
        int m = it * 16 + (t >> 4);
        int g = t & 15;
        float bv = __ldg(biasg + m);
        int n0s = 4 * g;
        float4 o;
        o.x = ob[(n0s + 0) * 129 + m] + bv;
        o.y = ob[(n0s + 1) * 129 + m] + bv;
        o.z = ob[(n0s + 2) * 129 + m] + bv;
        o.w = ob[(n0s + 3) * 129 + m] + bv;
        *reinterpret_cast<float4*>(outg + obase0 + ((long long)m << 14) + n0s) = o;
    }
}

extern "C" void kernel_launch(void* const* d_in, const int* in_sizes, int n_in,
                              void* d_out, int out_size) {
    const float *x = nullptr, *coef = nullptr, *w = nullptr, *bias = nullptr;
    for (int i = 0; i < n_in; ++i) {
        switch (in_sizes[i]) {
            case 8388608: x    = (const float*)d_in[i]; break;
            case 81:      coef = (const float*)d_in[i]; break;
            case 73728:   w    = (const float*)d_in[i]; break;
            case 128:     bias = (const float*)d_in[i]; break;
        }
    }
    prepack_w<<<36, 1024>>>(w);
    cudaFuncSetAttribute(sconv_mma_kernel,
                         cudaFuncAttributeMaxDynamicSharedMemorySize, SMEM_BYTES);
    dim3 grid(2, 128, 8);
    sconv_mma_kernel<<<grid, NTHREADS, SMEM_BYTES>>>(x, coef, bias, (float*)d_out);
}

// round 14
// speedup vs baseline: 4.4347x; 1.0245x over previous
#include <cuda_runtime.h>
#include <cuda_fp16.h>
#include <cstdint>

// Fused SConv via warp-level fp16 mma.sync GEMM.
// out[m=128, n] = sum_k W[m,k] * z[k,n], K=576, 64 pixels per CTA.
// R14: vectorized transposed coefficients (cfT[j][q] float4 pairs),
//      4-pixel-quad transform with shared x reads, K-split GEMM
//      (8 warps = 2ksp x 2nt x 2mh, 32n x 64m tiles), W frags from global.

#define NTHREADS 256
#define ZSTRIDE 1168         // 576*2 + 16 pad (ldmatrix conflict-free)
#define XR 72                // floats per x row (cols w0-4 .. w0+67)
#define XC 217               // floats per channel (3*72 + 1 pad, odd -> conflict-free)

#define OFF_Z   0            // 64 x 1168 = 74752
#define OFF_XS  74752        // 32*217*4 = 27776
#define OFF_OB  0            // epilogue [64][129] f32 (overlaps Z, after GEMM)
#define OFF_CF  102528       // cfT: 9 j x 8 q floats = 288B (16B aligned)
#define SMEM_BYTES 102912

// W fragment buffer: [mq 4][ch 9][ks 4][p 2][lane 32] x uint4 (4 regs)
__device__ __align__(16) uint32_t g_Wfrag[4 * 9 * 4 * 2 * 32 * 4];

__device__ __forceinline__ uint32_t smem_u32(const void* p) {
    uint32_t a;
    asm("{ .reg .u64 t; cvta.to.shared.u64 t, %1; cvt.u32.u64 %0, t; }" : "=r"(a) : "l"(p));
    return a;
}
__device__ __forceinline__ void ldm_x4(uint32_t* r, uint32_t addr) {
    asm volatile("ldmatrix.sync.aligned.m8n8.x4.shared.b16 {%0,%1,%2,%3}, [%4];"
                 : "=r"(r[0]), "=r"(r[1]), "=r"(r[2]), "=r"(r[3]) : "r"(addr));
}
__device__ __forceinline__ void mma16816(float* d, const uint32_t* a,
                                         uint32_t b0, uint32_t b1) {
    asm volatile("mma.sync.aligned.m16n8k16.row.col.f32.f16.f16.f32 "
                 "{%0,%1,%2,%3}, {%4,%5,%6,%7}, {%8,%9}, {%0,%1,%2,%3};"
                 : "+f"(d[0]), "+f"(d[1]), "+f"(d[2]), "+f"(d[3])
                 : "r"(a[0]), "r"(a[1]), "r"(a[2]), "r"(a[3]), "r"(b0), "r"(b1));
}

// ---------------- W pre-pack into fragment order (same as R13) ----------------
__global__ void prepack_w(const float* __restrict__ wg) {
    int idx = blockIdx.x * blockDim.x + threadIdx.x;   // 36864
    if (idx >= 4 * 9 * 4 * 2 * 32 * 4) return;
    int q = idx & 3;  int r = idx >> 2;
    int l = r & 31;   r >>= 5;
    int p = r & 1;    r >>= 1;
    int ks = r & 3;   r >>= 2;
    int ch = r % 9;
    int mq = r / 9;
    int m = mq * 32 + p * 16 + ((q >> 1) << 3) + (l >> 2);
    int k = ch * 64 + ks * 16 + ((q & 1) << 3) + ((l & 3) << 1);
    __half h0 = __float2half_rn(wg[m * 576 + k]);
    __half h1 = __float2half_rn(wg[m * 576 + k + 1]);
    g_Wfrag[idx] = (uint32_t)__half_as_ushort(h0) |
                   ((uint32_t)__half_as_ushort(h1) << 16);
}

// transform one pixel of one channel from register-held u[18] (3 rows x 6 cols)
__device__ __forceinline__ void transform_px(const float* __restrict__ u, int px,
                                             const float4* __restrict__ cfT4,
                                             float* __restrict__ out9) {
    float y0 = 0, y1 = 0, y2 = 0, y3 = 0, y4 = 0, y5 = 0, y6 = 0, y7 = 0;
#pragma unroll
    for (int j = 0; j < 9; ++j) {
        int r = j / 3, c2 = j % 3;
        float vj = u[r * 6 + px + c2];
        float4 cA = cfT4[j * 2];
        float4 cB = cfT4[j * 2 + 1];
        y0 = fmaf(cA.x, vj, y0); y1 = fmaf(cA.y, vj, y1);
        y2 = fmaf(cA.z, vj, y2); y3 = fmaf(cA.w, vj, y3);
        y4 = fmaf(cB.x, vj, y4); y5 = fmaf(cB.y, vj, y5);
        y6 = fmaf(cB.z, vj, y6); y7 = fmaf(cB.w, vj, y7);
    }
    float yv[8] = { y0, y1, y2, y3, y4, y5, y6, y7 };
#define CS(a, bb) { float _l = fminf(yv[a], yv[bb]); float _h = fmaxf(yv[a], yv[bb]); yv[a] = _l; yv[bb] = _h; }
    CS(0,1) CS(2,3) CS(4,5) CS(6,7)
    CS(0,2) CS(1,3) CS(4,6) CS(5,7)
    CS(1,2) CS(5,6)
    CS(0,4) CS(1,5) CS(2,6) CS(3,7)
    CS(2,4) CS(3,5)
    CS(1,2) CS(3,4) CS(5,6)
#undef CS
    out9[0] = yv[0]; out9[1] = yv[1]; out9[2] = yv[2]; out9[3] = yv[3];
    out9[4] = u[6 + px + 1];   // center v4
    out9[5] = yv[4]; out9[6] = yv[5]; out9[7] = yv[6]; out9[8] = yv[7];
}

// ---------------- main fused kernel ----------------
__global__ __launch_bounds__(NTHREADS, 2)
void sconv_mma_kernel(const float* __restrict__ xg,
                      const float* __restrict__ coefg,
                      const float* __restrict__ biasg,
                      float* __restrict__ outg) {
    extern __shared__ __align__(1024) unsigned char smem[];
    const uint32_t sb = smem_u32(smem);
    const int t   = threadIdx.x;
    const int wid = t >> 5;
    const int lid = t & 31;
    const int b   = blockIdx.z;
    const int h   = blockIdx.y;
    const int w0  = blockIdx.x * 64;

    float* xs = reinterpret_cast<float*>(smem + OFF_XS);
    float* cfT = reinterpret_cast<float*>(smem + OFF_CF);
    const float4* cfT4 = reinterpret_cast<const float4*>(smem + OFF_CF);

    // cfT[j*8 + q] = Coef[ri(q)][j], ri = q + (q>=4)
    if (t < 72) {
        int j = t >> 3, q = t & 7;
        int ri = q + (q >= 4 ? 1 : 0);
        cfT[j * 8 + q] = coefg[ri * 9 + j];
    }

    // warp roles: ksp = wid>>2, nt = wid&1, mh = (wid>>1)&1
    const int ksp = wid >> 2;
    const int nt  = wid & 1;
    const int mh  = (wid >> 1) & 1;
    const int n0  = nt * 32;

    // A (z) ldmatrix x4 addressing: 16n x 16k tiles (nb=1 adds 16*ZSTRIDE)
    const int rA   = lid & 7;
    const int matA = lid >> 3;
    const uint32_t aBase = sb + OFF_Z +
        (uint32_t)(n0 + rA + ((matA & 1) << 3)) * ZSTRIDE + (((matA >> 1) << 3) << 1);

    const uint4* wf0 = reinterpret_cast<const uint4*>(g_Wfrag) + lid;

    // transform lane roles: cp = ch-pair, q4 = pixel quad
    const int cp  = t & 15;
    const int q4  = t >> 4;           // 0..15
    const int nn0 = q4 * 4;

    // ---- build full z (K=576) in two 32-channel phases
    for (int cc = 0; cc < 2; ++cc) {
        __syncthreads();   // xs region free

        // stage x: ch = t>>3, lane8 = t&7; 18 vec x 3 rows per channel
        {
            const float* xb = xg + (((long long)b * 64 + cc * 32) << 14);
            int c    = t >> 3;
            int l8   = t & 7;
            const float* xc = xb + (c << 14);
            float* xd = xs + c * XC;
#pragma unroll
            for (int j0 = 0; j0 < 7; ++j0) {
                int j = l8 + j0 * 8;
                if (j < 54) {
                    int r = j / 18, v = j % 18;
                    int gr = h + r - 1;
                    int gcb = w0 - 4 + 4 * v;
                    float4 val = make_float4(0.f, 0.f, 0.f, 0.f);
                    // whole-vector validity (w0 % 64 == 0 guarantees no partial vecs)
                    if ((unsigned)gr < 128u && gcb >= 0 && gcb + 3 < 128)
                        val = *reinterpret_cast<const float4*>(xc + (gr << 7) + gcb);
                    float* d = xd + r * XR + 4 * v;
                    d[0] = val.x; d[1] = val.y; d[2] = val.z; d[3] = val.w;
                }
            }
        }
        __syncthreads();

        // transform: thread = (ch pair 2cp,2cp+1) x (pixel quad nn0..nn0+3)
        {
            const float* xr0 = xs + (2 * cp) * XC;
            const float* xr1 = xr0 + XC;
            float u0[18], u1[18];
#pragma unroll
            for (int r = 0; r < 3; ++r)
#pragma unroll
                for (int c2 = 0; c2 < 6; ++c2) {
                    u0[r * 6 + c2] = xr0[r * XR + nn0 + 3 + c2];
                    u1[r * 6 + c2] = xr1[r * XR + nn0 + 3 + c2];
                }
            const uint32_t zcol = (uint32_t)(cc * 32 + 2 * cp) * 18;
#pragma unroll
            for (int px = 0; px < 4; ++px) {
                float s18[18];
                transform_px(u0, px, cfT4, s18);
                transform_px(u1, px, cfT4, s18 + 9);
                uint32_t* zh = reinterpret_cast<uint32_t*>(
                    smem + OFF_Z + (nn0 + px) * ZSTRIDE + zcol);
#pragma unroll
                for (int j = 0; j < 9; ++j) {
                    __half a  = __float2half_rn(s18[2 * j]);
                    __half c2 = __float2half_rn(s18[2 * j + 1]);
                    zh[j] = (uint32_t)__half_as_ushort(a) |
                            ((uint32_t)__half_as_ushort(c2) << 16);
                }
            }
        }
    }
    __syncthreads();   // z ready

    // ---- GEMM: K-split halves (18 k-steps of 16 each), B frags from L2
    float acc[2][8][4];
#pragma unroll
    for (int i = 0; i < 2; ++i)
#pragma unroll
        for (int j = 0; j < 8; ++j)
#pragma unroll
            for (int q = 0; q < 4; ++q) acc[i][j][q] = 0.0f;

#pragma unroll 2
    for (int ks = ksp * 18; ks < ksp * 18 + 18; ++ks) {
        uint32_t aAddr = aBase + (uint32_t)ks * 32;
        uint32_t a0[4], a1[4];
        ldm_x4(a0, aAddr);
        ldm_x4(a1, aAddr + 16 * ZSTRIDE);
        int ch = ks >> 2, ksi = ks & 3;
#pragma unroll
        for (int mqi = 0; mqi < 2; ++mqi) {
            const uint4* wp = wf0 + (uint32_t)((((2 * mh + mqi) * 9 + ch) * 4 + ksi) * 2) * 32;
            uint4 b0 = __ldg(wp);
            uint4 b1 = __ldg(wp + 32);
            int mb0 = mqi * 4;
            mma16816(acc[0][mb0 + 0], a0, b0.x, b0.y);
            mma16816(acc[0][mb0 + 1], a0, b0.z, b0.w);
            mma16816(acc[1][mb0 + 0], a1, b0.x, b0.y);
            mma16816(acc[1][mb0 + 1], a1, b0.z, b0.w);
            mma16816(acc[0][mb0 + 2], a0, b1.x, b1.y);
            mma16816(acc[0][mb0 + 3], a0, b1.z, b1.w);
            mma16816(acc[1][mb0 + 2], a1, b1.x, b1.y);
            mma16816(acc[1][mb0 + 3], a1, b1.z, b1.w);
        }
    }
    __syncthreads();   // all z reads done; Z region -> epilogue buffer

    // ---- epilogue: ksp0 stores partials, ksp1 accumulates, then coalesced out
    float* ob = reinterpret_cast<float*>(smem + OFF_OB);
    const int mcb = mh * 64 + ((lid & 3) << 1);
    if (ksp == 0) {
#pragma unroll
        for (int nb = 0; nb < 2; ++nb) {
            int r0 = n0 + nb * 16 + (lid >> 2);
#pragma unroll
            for (int mb = 0; mb < 8; ++mb) {
                int mc = mcb + mb * 8;
                ob[r0 * 129 + mc]           = acc[nb][mb][0];
                ob[r0 * 129 + mc + 1]       = acc[nb][mb][1];
                ob[(r0 + 8) * 129 + mc]     = acc[nb][mb][2];
                ob[(r0 + 8) * 129 + mc + 1] = acc[nb][mb][3];
            }
        }
    }
    __syncthreads();
    if (ksp == 1) {
#pragma unroll
        for (int nb = 0; nb < 2; ++nb) {
            int r0 = n0 + nb * 16 + (lid >> 2);
#pragma unroll
            for (int mb = 0; mb < 8; ++mb) {
                int mc = mcb + mb * 8;
                ob[r0 * 129 + mc]           += acc[nb][mb][0];
                ob[r0 * 129 + mc + 1]       += acc[nb][mb][1];
                ob[(r0 + 8) * 129 + mc]     += acc[nb][mb][2];
                ob[(r0 + 8) * 129 + mc + 1] += acc[nb][mb][3];
            }
        }
    }
    __syncthreads();

    const long long obase0 = (((long long)b * 128) * 128 + h) * 128 + w0;
#pragma unroll
    for (int it = 0; it < 8; ++it) {
        int m = it * 16 + (t >> 4);
        int g = t & 15;
        float bv = __ldg(biasg + m);
        int n0s = 4 * g;
        float4 o;
        o.x = ob[(n0s + 0) * 129 + m] + bv;
        o.y = ob[(n0s + 1) * 129 + m] + bv;
        o.z = ob[(n0s + 2) * 129 + m] + bv;
        o.w = ob[(n0s + 3) * 129 + m] + bv;
        *reinterpret_cast<float4*>(outg + obase0 + ((long long)m << 14) + n0s) = o;
    }
}

extern "C" void kernel_launch(void* const* d_in, const int* in_sizes, int n_in,
                              void* d_out, int out_size) {
    const float *x = nullptr, *coef = nullptr, *w = nullptr, *bias = nullptr;
    for (int i = 0; i < n_in; ++i) {
        switch (in_sizes[i]) {
            case 8388608: x    = (const float*)d_in[i]; break;
            case 81:      coef = (const float*)d_in[i]; break;
            case 73728:   w    = (const float*)d_in[i]; break;
            case 128:     bias = (const float*)d_in[i]; break;
        }
    }
    prepack_w<<<36, 1024>>>(w);
    cudaFuncSetAttribute(sconv_mma_kernel,
                         cudaFuncAttributeMaxDynamicSharedMemorySize, SMEM_BYTES);
    dim3 grid(2, 128, 8);
    sconv_mma_kernel<<<grid, NTHREADS, SMEM_BYTES>>>(x, coef, bias, (float*)d_out);
}